// round 2
// baseline (speedup 1.0000x reference)
#include <cuda_runtime.h>

// Problem constants
constexpr int NXc = 128, NYc = 128, NTc = 16, NCc = 8, NRADc = 2048;
constexpr int NNc = NCc * NYc;                    // 1024 fused (coil,y) columns
constexpr float SCALE2 = 1.0f / (128.0f * 128.0f); // 'ortho' scale applied twice

// Static device scratch (allocation-free per harness rules)
__device__ float2 g_Ex[NTc * NRADc * NXc];                 // 32 MB
__device__ float2 g_Ey[NTc * NRADc * NYc];                 // 32 MB
__device__ float2 g_src[NTc * NXc * NNc];                  // 16 MB
__device__ float2 g_t[(size_t)NTc * NRADc * NNc];          // 256 MB
__device__ float2 g_xim[NTc * NXc * NNc];                  // 16 MB

__device__ __forceinline__ float2 cmulf2(float2 a, float2 b) {
    return make_float2(a.x * b.x - a.y * b.y, a.x * b.y + a.y * b.x);
}

// ---------------------------------------------------------------------------
// K1: phase tables Ex[t][k][x] = exp(-i*k_x*(x-64)), Ey likewise.
// One warp per (t,k). One sincosf per table; powers via repeated squaring.
// ---------------------------------------------------------------------------
__global__ void phase_kernel(const float* __restrict__ ktraj) {
    int gtid = blockIdx.x * blockDim.x + threadIdx.x;
    int wid = gtid >> 5, lane = gtid & 31;
    if (wid >= NRADc * NTc) return;
    int t = wid % NTc, k = wid / NTc;

    #pragma unroll
    for (int comp = 0; comp < 2; ++comp) {
        float kv = ktraj[((size_t)comp * NRADc + k) * NTc + t];
        float s, c;
        sincosf(kv, &s, &c);
        float2 v = make_float2(c, s);        // exp(+i*kv)
        float2 pw[7];
        pw[0] = v;
        #pragma unroll
        for (int j = 1; j < 7; ++j) pw[j] = cmulf2(pw[j - 1], pw[j - 1]); // v^(2^j)
        // lane handles x = lane, lane+32, lane+64, lane+96; xs = x - 64.
        // base = exp(-i*kv*(lane-64)) = v^(64-lane), m in [33,64]
        int m = 64 - lane;
        float2 base = make_float2(1.f, 0.f);
        #pragma unroll
        for (int b = 0; b < 7; ++b)
            if ((m >> b) & 1) base = cmulf2(base, pw[b]);
        float2 step = make_float2(pw[5].x, -pw[5].y);   // exp(-i*32*kv)
        float2* out = (comp == 0 ? g_Ex : g_Ey) + ((size_t)t * NRADc + k) * 128;
        float2 cur = base;
        #pragma unroll
        for (int j = 0; j < 4; ++j) {
            out[lane + 32 * j] = cur;
            cur = cmulf2(cur, step);
        }
    }
}

// ---------------------------------------------------------------------------
// K2: src[t][x][c*NY+y] = smap[c,x,y] * img[x,y,t]
// ---------------------------------------------------------------------------
__global__ void src_kernel(const float* __restrict__ xin, const float* __restrict__ csmap) {
    int i = blockIdx.x * blockDim.x + threadIdx.x;
    if (i >= NTc * NXc * NNc) return;
    int n = i % NNc;
    int xx = (i / NNc) % NXc;
    int t = i / (NNc * NXc);
    int c = n / NYc, y = n % NYc;
    float ir = xin[(((size_t)0 * NXc + xx) * NYc + y) * NTc + t];
    float ii = xin[(((size_t)1 * NXc + xx) * NYc + y) * NTc + t];
    float sr = csmap[(((size_t)c * 2 + 0) * NXc + xx) * NYc + y];
    float si = csmap[(((size_t)c * 2 + 1) * NXc + xx) * NYc + y];
    g_src[i] = cmulf2(make_float2(sr, si), make_float2(ir, ii));
}

// ---------------------------------------------------------------------------
// Batched complex GEMM: C[m,n] = sum_k op(A)[m,k] * B[k,n], per frame (blockIdx.z)
// A_KMAJOR: A stored [K][M] (M contiguous); else [M][K] (K contiguous).
// CONJ_A: conjugate A. Tiles 64x64x16, 256 threads, 4x4 complex per thread.
// ---------------------------------------------------------------------------
template <bool A_KMAJOR, bool CONJ_A>
__global__ void cgemm64(const float2* __restrict__ A, const float2* __restrict__ B,
                        float2* __restrict__ C, int M, int N, int K,
                        size_t sA, size_t sB, size_t sC) {
    constexpr int BM = 64, BN = 64, BK = 16;
    __shared__ float2 As[BK][BM + 2];
    __shared__ float2 Bs[BK][BN];
    int f = blockIdx.z;
    A += (size_t)f * sA;
    B += (size_t)f * sB;
    C += (size_t)f * sC;
    int m0 = blockIdx.y * BM, n0 = blockIdx.x * BN;
    int tid = threadIdx.x;
    int tx = tid & 15, ty = tid >> 4;

    float accR[4][4] = {}, accI[4][4] = {};

    for (int k0 = 0; k0 < K; k0 += BK) {
        if (A_KMAJOR) {
            #pragma unroll
            for (int p = 0; p < 4; ++p) {
                int col = tid & 63, kr = (tid >> 6) + p * 4;
                float2 v = A[(size_t)(k0 + kr) * M + m0 + col];
                if (CONJ_A) v.y = -v.y;
                As[kr][col] = v;
            }
        } else {
            #pragma unroll
            for (int p = 0; p < 4; ++p) {
                int col = tid & 15, row = (tid >> 4) + p * 16;
                float2 v = A[(size_t)(m0 + row) * K + k0 + col];
                if (CONJ_A) v.y = -v.y;
                As[col][row] = v;
            }
        }
        #pragma unroll
        for (int p = 0; p < 4; ++p) {
            int col = tid & 63, kr = (tid >> 6) + p * 4;
            Bs[kr][col] = B[(size_t)(k0 + kr) * N + n0 + col];
        }
        __syncthreads();

        #pragma unroll
        for (int kk = 0; kk < BK; ++kk) {
            float aR[4], aI[4], bR[4], bI[4];
            #pragma unroll
            for (int i = 0; i < 4; ++i) {
                float2 a = As[kk][ty * 4 + i];
                aR[i] = a.x; aI[i] = a.y;
            }
            #pragma unroll
            for (int j = 0; j < 4; ++j) {
                float2 b = Bs[kk][tx * 4 + j];
                bR[j] = b.x; bI[j] = b.y;
            }
            #pragma unroll
            for (int i = 0; i < 4; ++i)
                #pragma unroll
                for (int j = 0; j < 4; ++j) {
                    accR[i][j] = fmaf(aR[i], bR[j], accR[i][j]);
                    accR[i][j] = fmaf(-aI[i], bI[j], accR[i][j]);
                    accI[i][j] = fmaf(aR[i], bI[j], accI[i][j]);
                    accI[i][j] = fmaf(aI[i], bR[j], accI[i][j]);
                }
        }
        __syncthreads();
    }
    #pragma unroll
    for (int i = 0; i < 4; ++i)
        #pragma unroll
        for (int j = 0; j < 4; ++j)
            C[(size_t)(m0 + ty * 4 + i) * N + n0 + tx * 4 + j] =
                make_float2(accR[i][j], accI[i][j]);
}

// ---------------------------------------------------------------------------
// K3 (in place on g_t): per (t,k):
//   g[c] = (sum_y Ey[k,y]*t[k,c,y]) * dcomp[k,t] * scale^2
//   t2[k,c,y] = conj(Ey[k,y]) * g[c]
// One warp per (t,k); lane covers 4 y-points.
// ---------------------------------------------------------------------------
__global__ void middle_kernel(const float* __restrict__ dcomp) {
    int gtid = blockIdx.x * blockDim.x + threadIdx.x;
    int wid = gtid >> 5, lane = gtid & 31;
    if (wid >= NRADc * NTc) return;
    int t = wid % NTc, k = wid / NTc;
    const float2* ey = g_Ey + ((size_t)t * NRADc + k) * NYc;
    float2* tp = g_t + ((size_t)t * NRADc + k) * NNc;
    float2 e[4];
    #pragma unroll
    for (int j = 0; j < 4; ++j) e[j] = ey[lane + 32 * j];
    float ds = dcomp[(size_t)k * NTc + t] * SCALE2;

    for (int c = 0; c < NCc; ++c) {
        float2 v[4];
        #pragma unroll
        for (int j = 0; j < 4; ++j) v[j] = tp[c * NYc + lane + 32 * j];
        float sr = 0.f, si = 0.f;
        #pragma unroll
        for (int j = 0; j < 4; ++j) {
            sr += e[j].x * v[j].x - e[j].y * v[j].y;
            si += e[j].x * v[j].y + e[j].y * v[j].x;
        }
        #pragma unroll
        for (int off = 16; off; off >>= 1) {
            sr += __shfl_xor_sync(0xffffffffu, sr, off);
            si += __shfl_xor_sync(0xffffffffu, si, off);
        }
        float gr = sr * ds, gi = si * ds;
        #pragma unroll
        for (int j = 0; j < 4; ++j)
            tp[c * NYc + lane + 32 * j] =
                make_float2(e[j].x * gr + e[j].y * gi, e[j].x * gi - e[j].y * gr);
    }
}

// ---------------------------------------------------------------------------
// K5: out[comp][x][y][t] = sum_c conj(smap[c,x,y]) * xim[t][x][c*NY+y]
// ---------------------------------------------------------------------------
__global__ void combine_kernel(const float* __restrict__ csmap, float* __restrict__ out) {
    int i = blockIdx.x * blockDim.x + threadIdx.x;
    if (i >= NTc * NXc * NYc) return;
    int y = i % NYc;
    int xx = (i / NYc) % NXc;
    int t = i / (NYc * NXc);
    const float2* xim = g_xim + ((size_t)t * NXc + xx) * NNc;
    float accR = 0.f, accI = 0.f;
    #pragma unroll
    for (int c = 0; c < NCc; ++c) {
        float sr = csmap[(((size_t)c * 2 + 0) * NXc + xx) * NYc + y];
        float si = csmap[(((size_t)c * 2 + 1) * NXc + xx) * NYc + y];
        float2 v = xim[c * NYc + y];
        accR += sr * v.x + si * v.y;
        accI += sr * v.y - si * v.x;
    }
    size_t o = ((size_t)xx * NYc + y) * NTc + t;
    out[o] = accR;
    out[(size_t)NXc * NYc * NTc + o] = accI;
}

// ---------------------------------------------------------------------------
extern "C" void kernel_launch(void* const* d_in, const int* in_sizes, int n_in,
                              void* d_out, int out_size) {
    // Disambiguate inputs by element count (all four are distinct)
    const float *x = nullptr, *ktraj = nullptr, *csmap = nullptr, *dcomp = nullptr;
    for (int i = 0; i < n_in; ++i) {
        switch (in_sizes[i]) {
            case 2 * NXc * NYc * NTc:      x = (const float*)d_in[i]; break;     // 524288
            case 2 * NRADc * NTc:          ktraj = (const float*)d_in[i]; break; // 65536
            case NCc * 2 * NXc * NYc:      csmap = (const float*)d_in[i]; break; // 262144
            case NRADc * NTc:              dcomp = (const float*)d_in[i]; break; // 32768
            default: break;
        }
    }
    float* out = (float*)d_out;

    float2 *pEx = nullptr, *pSrc = nullptr, *pT = nullptr, *pXim = nullptr;
    cudaGetSymbolAddress((void**)&pEx, g_Ex);
    cudaGetSymbolAddress((void**)&pSrc, g_src);
    cudaGetSymbolAddress((void**)&pT, g_t);
    cudaGetSymbolAddress((void**)&pXim, g_xim);

    // K1: phase tables (32768 warps)
    phase_kernel<<<(NRADc * NTc * 32) / 256, 256>>>(ktraj);
    // K2: coil-weighted source images
    src_kernel<<<(NTc * NXc * NNc) / 256, 256>>>(x, csmap);
    // Forward NDFT over x: t = Ex @ src   (M=2048, N=1024, K=128, per frame)
    cgemm64<false, false><<<dim3(NNc / 64, NRADc / 64, NTc), 256>>>(
        pEx, pSrc, pT, NRADc, NNc, NXc,
        (size_t)NRADc * NXc, (size_t)NXc * NNc, (size_t)NRADc * NNc);
    // Middle: Ey-projection, dcomp * scale^2, conj(Ey) expansion (in place)
    middle_kernel<<<(NRADc * NTc * 32) / 256, 256>>>(dcomp);
    // Adjoint NDFT over x: xim = conj(Ex)^T @ t2   (M=128, N=1024, K=2048)
    cgemm64<true, true><<<dim3(NNc / 64, NXc / 64, NTc), 256>>>(
        pEx, pT, pXim, NXc, NNc, NRADc,
        (size_t)NRADc * NXc, (size_t)NRADc * NNc, (size_t)NXc * NNc);
    // Coil combine with conj sensitivities
    combine_kernel<<<(NTc * NXc * NYc) / 256, 256>>>(csmap, out);
}

// round 6
// speedup vs baseline: 1.0764x; 1.0764x over previous
#include <cuda_runtime.h>
#include <cstring>

// Problem constants
constexpr int NXc = 128, NYc = 128, NTc = 16, NCc = 8, NRADc = 2048;
constexpr int NNc = NCc * NYc;                    // 1024 fused (coil,y) columns
constexpr float SCALE2 = 1.0f / (128.0f * 128.0f); // 'ortho' scale applied twice

// Static device scratch (allocation-free per harness rules)
__device__ float2 g_Ex[NTc * NRADc * NXc];                 // 32 MB
__device__ float2 g_Ey[NTc * NRADc * NYc];                 // 32 MB
__device__ float2 g_src[NTc * NXc * NNc];                  // 16 MB
__device__ float2 g_t[(size_t)NTc * NRADc * NNc];          // 256 MB
__device__ float2 g_xim[NTc * NXc * NNc];                  // 16 MB

__device__ __forceinline__ float2 cmulf2(float2 a, float2 b) {
    return make_float2(a.x * b.x - a.y * b.y, a.x * b.y + a.y * b.x);
}

// ---- packed f32x2 helpers -------------------------------------------------
__device__ __forceinline__ unsigned long long pack2(float lo, float hi) {
    unsigned long long r;
    asm("mov.b64 %0, {%1, %2};" : "=l"(r) : "f"(lo), "f"(hi));
    return r;
}
__device__ __forceinline__ void ffma2(unsigned long long& acc,
                                      unsigned long long a, unsigned long long b) {
    asm("fma.rn.f32x2 %0, %1, %2, %0;" : "+l"(acc) : "l"(a), "l"(b));
}
__device__ __forceinline__ unsigned long long f2u(float2 v) {
    unsigned long long r; memcpy(&r, &v, 8); return r;
}
__device__ __forceinline__ float2 u2f(unsigned long long v) {
    float2 r; memcpy(&r, &v, 8); return r;
}

// ---------------------------------------------------------------------------
// K1: phase tables Ex[t][k][x] = exp(-i*k_x*(x-64)), Ey likewise.
// One warp per (t,k). One sincosf per table; powers via repeated squaring.
// ---------------------------------------------------------------------------
__global__ void phase_kernel(const float* __restrict__ ktraj) {
    int gtid = blockIdx.x * blockDim.x + threadIdx.x;
    int wid = gtid >> 5, lane = gtid & 31;
    if (wid >= NRADc * NTc) return;
    int t = wid % NTc, k = wid / NTc;

    #pragma unroll
    for (int comp = 0; comp < 2; ++comp) {
        float kv = ktraj[((size_t)comp * NRADc + k) * NTc + t];
        float s, c;
        sincosf(kv, &s, &c);
        float2 v = make_float2(c, s);        // exp(+i*kv)
        float2 pw[7];
        pw[0] = v;
        #pragma unroll
        for (int j = 1; j < 7; ++j) pw[j] = cmulf2(pw[j - 1], pw[j - 1]); // v^(2^j)
        // lane handles x = lane, lane+32, lane+64, lane+96; xs = x - 64.
        // base = exp(-i*kv*(lane-64)) = v^(64-lane), m in [33,64]
        int m = 64 - lane;
        float2 base = make_float2(1.f, 0.f);
        #pragma unroll
        for (int b = 0; b < 7; ++b)
            if ((m >> b) & 1) base = cmulf2(base, pw[b]);
        float2 step = make_float2(pw[5].x, -pw[5].y);   // exp(-i*32*kv)
        float2* out = (comp == 0 ? g_Ex : g_Ey) + ((size_t)t * NRADc + k) * 128;
        float2 cur = base;
        #pragma unroll
        for (int j = 0; j < 4; ++j) {
            out[lane + 32 * j] = cur;
            cur = cmulf2(cur, step);
        }
    }
}

// ---------------------------------------------------------------------------
// K2: src[t][x][c*NY+y] = smap[c,x,y] * img[x,y,t]
// ---------------------------------------------------------------------------
__global__ void src_kernel(const float* __restrict__ xin, const float* __restrict__ csmap) {
    int i = blockIdx.x * blockDim.x + threadIdx.x;
    if (i >= NTc * NXc * NNc) return;
    int n = i % NNc;
    int xx = (i / NNc) % NXc;
    int t = i / (NNc * NXc);
    int c = n / NYc, y = n % NYc;
    float ir = xin[(((size_t)0 * NXc + xx) * NYc + y) * NTc + t];
    float ii = xin[(((size_t)1 * NXc + xx) * NYc + y) * NTc + t];
    float sr = csmap[(((size_t)c * 2 + 0) * NXc + xx) * NYc + y];
    float si = csmap[(((size_t)c * 2 + 1) * NXc + xx) * NYc + y];
    g_src[i] = cmulf2(make_float2(sr, si), make_float2(ir, ii));
}

// ---------------------------------------------------------------------------
// Batched complex GEMM using packed f32x2 FMAs (2 real MACs / instruction).
// C[m,n] = sum_k op(A)[m,k] * B[k,n], per frame (blockIdx.z).
//   A_KMAJOR: A stored [K][M]; else [M][K]. CONJ_A: conjugate A.
// Tile: BM=64, BN=64, BK=16, 128 threads, 4x8 complex per thread.
// Each output's (Re,Im) lives in one 64-bit packed accumulator:
//   acc += (aR,aR)*(bR,bI) + (aI,aI)*(-bI,bR)
// Thread's 8 columns are stride-8 so all Bs reads are 8-address broadcasts.
// ---------------------------------------------------------------------------
template <bool A_KMAJOR, bool CONJ_A>
__global__ void __launch_bounds__(128)
cgemm_f32x2(const float2* __restrict__ A, const float2* __restrict__ B,
            float2* __restrict__ C, int M, int N, int K,
            size_t sA, size_t sB, size_t sC) {
    constexpr int BM = 64, BN = 64, BK = 16;
    __shared__ float2 As[BK][BM + 1];   // +1 kills 16-way store conflict (KMAJOR=false path)
    __shared__ float2 Bs[BK][BN];
    int f = blockIdx.z;
    A += (size_t)f * sA;
    B += (size_t)f * sB;
    C += (size_t)f * sC;
    int m0 = blockIdx.y * BM, n0 = blockIdx.x * BN;
    int tid = threadIdx.x;
    int tx = tid & 7, ty = tid >> 3;    // tx: 8 col-groups, ty: 16 row-groups

    unsigned long long acc[4][8];
    #pragma unroll
    for (int i = 0; i < 4; ++i)
        #pragma unroll
        for (int j = 0; j < 8; ++j) acc[i][j] = 0ull;

    float2 ra[8], rb[8];

    auto loadA = [&](int k0) {
        #pragma unroll
        for (int p = 0; p < 8; ++p) {
            int idx = p * 128 + tid;
            if (A_KMAJOR) {
                int kr = idx >> 6, col = idx & 63;
                ra[p] = A[(size_t)(k0 + kr) * M + m0 + col];
            } else {
                int kr = idx & 15, row = idx >> 4;
                ra[p] = A[(size_t)(m0 + row) * K + k0 + kr];
            }
        }
    };
    auto loadB = [&](int k0) {
        #pragma unroll
        for (int p = 0; p < 8; ++p) {
            int idx = p * 128 + tid;
            int kr = idx >> 6, col = idx & 63;
            rb[p] = B[(size_t)(k0 + kr) * N + n0 + col];
        }
    };
    auto stageA = [&]() {
        #pragma unroll
        for (int p = 0; p < 8; ++p) {
            int idx = p * 128 + tid;
            float2 v = ra[p];
            if (CONJ_A) v.y = -v.y;
            if (A_KMAJOR) As[idx >> 6][idx & 63] = v;
            else          As[idx & 15][idx >> 4] = v;
        }
    };
    auto stageB = [&]() {
        #pragma unroll
        for (int p = 0; p < 8; ++p) {
            int idx = p * 128 + tid;
            Bs[idx >> 6][idx & 63] = rb[p];
        }
    };

    loadA(0);
    loadB(0);

    for (int k0 = 0; k0 < K; k0 += BK) {
        stageA();
        stageB();
        __syncthreads();
        if (k0 + BK < K) { loadA(k0 + BK); loadB(k0 + BK); }

        #pragma unroll
        for (int kk = 0; kk < BK; ++kk) {
            unsigned long long b1[8], b2[8];
            #pragma unroll
            for (int j = 0; j < 8; ++j) {
                float2 b = Bs[kk][tx + 8 * j];
                b1[j] = f2u(b);
                b2[j] = pack2(-b.y, b.x);
            }
            #pragma unroll
            for (int i = 0; i < 4; ++i) {
                float2 a = As[kk][ty * 4 + i];
                unsigned long long aR = pack2(a.x, a.x);
                unsigned long long aI = pack2(a.y, a.y);
                #pragma unroll
                for (int j = 0; j < 8; ++j) {
                    ffma2(acc[i][j], aR, b1[j]);
                    ffma2(acc[i][j], aI, b2[j]);
                }
            }
        }
        __syncthreads();
    }
    #pragma unroll
    for (int i = 0; i < 4; ++i)
        #pragma unroll
        for (int j = 0; j < 8; ++j)
            C[(size_t)(m0 + ty * 4 + i) * N + n0 + tx + 8 * j] = u2f(acc[i][j]);
}

// ---------------------------------------------------------------------------
// K3 (in place on g_t): per (t,k):
//   g[c] = (sum_y Ey[k,y]*t[k,c,y]) * dcomp[k,t] * scale^2
//   t2[k,c,y] = conj(Ey[k,y]) * g[c]
// One warp per (t,k); lane covers 4 y-points.
// ---------------------------------------------------------------------------
__global__ void middle_kernel(const float* __restrict__ dcomp) {
    int gtid = blockIdx.x * blockDim.x + threadIdx.x;
    int wid = gtid >> 5, lane = gtid & 31;
    if (wid >= NRADc * NTc) return;
    int t = wid % NTc, k = wid / NTc;
    const float2* ey = g_Ey + ((size_t)t * NRADc + k) * NYc;
    float2* tp = g_t + ((size_t)t * NRADc + k) * NNc;
    float2 e[4];
    #pragma unroll
    for (int j = 0; j < 4; ++j) e[j] = ey[lane + 32 * j];
    float ds = dcomp[(size_t)k * NTc + t] * SCALE2;

    for (int c = 0; c < NCc; ++c) {
        float2 v[4];
        #pragma unroll
        for (int j = 0; j < 4; ++j) v[j] = tp[c * NYc + lane + 32 * j];
        float sr = 0.f, si = 0.f;
        #pragma unroll
        for (int j = 0; j < 4; ++j) {
            sr += e[j].x * v[j].x - e[j].y * v[j].y;
            si += e[j].x * v[j].y + e[j].y * v[j].x;
        }
        #pragma unroll
        for (int off = 16; off; off >>= 1) {
            sr += __shfl_xor_sync(0xffffffffu, sr, off);
            si += __shfl_xor_sync(0xffffffffu, si, off);
        }
        float gr = sr * ds, gi = si * ds;
        #pragma unroll
        for (int j = 0; j < 4; ++j)
            tp[c * NYc + lane + 32 * j] =
                make_float2(e[j].x * gr + e[j].y * gi, e[j].x * gi - e[j].y * gr);
    }
}

// ---------------------------------------------------------------------------
// K5: out[comp][x][y][t] = sum_c conj(smap[c,x,y]) * xim[t][x][c*NY+y]
// ---------------------------------------------------------------------------
__global__ void combine_kernel(const float* __restrict__ csmap, float* __restrict__ out) {
    int i = blockIdx.x * blockDim.x + threadIdx.x;
    if (i >= NTc * NXc * NYc) return;
    int y = i % NYc;
    int xx = (i / NYc) % NXc;
    int t = i / (NYc * NXc);
    const float2* xim = g_xim + ((size_t)t * NXc + xx) * NNc;
    float accR = 0.f, accI = 0.f;
    #pragma unroll
    for (int c = 0; c < NCc; ++c) {
        float sr = csmap[(((size_t)c * 2 + 0) * NXc + xx) * NYc + y];
        float si = csmap[(((size_t)c * 2 + 1) * NXc + xx) * NYc + y];
        float2 v = xim[c * NYc + y];
        accR += sr * v.x + si * v.y;
        accI += sr * v.y - si * v.x;
    }
    size_t o = ((size_t)xx * NYc + y) * NTc + t;
    out[o] = accR;
    out[(size_t)NXc * NYc * NTc + o] = accI;
}

// ---------------------------------------------------------------------------
extern "C" void kernel_launch(void* const* d_in, const int* in_sizes, int n_in,
                              void* d_out, int out_size) {
    // Disambiguate inputs by element count (all four are distinct)
    const float *x = nullptr, *ktraj = nullptr, *csmap = nullptr, *dcomp = nullptr;
    for (int i = 0; i < n_in; ++i) {
        switch (in_sizes[i]) {
            case 2 * NXc * NYc * NTc:      x = (const float*)d_in[i]; break;     // 524288
            case 2 * NRADc * NTc:          ktraj = (const float*)d_in[i]; break; // 65536
            case NCc * 2 * NXc * NYc:      csmap = (const float*)d_in[i]; break; // 262144
            case NRADc * NTc:              dcomp = (const float*)d_in[i]; break; // 32768
            default: break;
        }
    }
    float* out = (float*)d_out;

    float2 *pEx = nullptr, *pSrc = nullptr, *pT = nullptr, *pXim = nullptr;
    cudaGetSymbolAddress((void**)&pEx, g_Ex);
    cudaGetSymbolAddress((void**)&pSrc, g_src);
    cudaGetSymbolAddress((void**)&pT, g_t);
    cudaGetSymbolAddress((void**)&pXim, g_xim);

    // K1: phase tables (32768 warps)
    phase_kernel<<<(NRADc * NTc * 32) / 256, 256>>>(ktraj);
    // K2: coil-weighted source images
    src_kernel<<<(NTc * NXc * NNc) / 256, 256>>>(x, csmap);
    // Forward NDFT over x: t = Ex @ src   (M=2048, N=1024, K=128, per frame)
    cgemm_f32x2<false, false><<<dim3(NNc / 64, NRADc / 64, NTc), 128>>>(
        pEx, pSrc, pT, NRADc, NNc, NXc,
        (size_t)NRADc * NXc, (size_t)NXc * NNc, (size_t)NRADc * NNc);
    // Middle: Ey-projection, dcomp * scale^2, conj(Ey) expansion (in place)
    middle_kernel<<<(NRADc * NTc * 32) / 256, 256>>>(dcomp);
    // Adjoint NDFT over x: xim = conj(Ex)^T @ t2   (M=128, N=1024, K=2048)
    cgemm_f32x2<true, true><<<dim3(NNc / 64, NXc / 64, NTc), 128>>>(
        pEx, pT, pXim, NXc, NNc, NRADc,
        (size_t)NRADc * NXc, (size_t)NRADc * NNc, (size_t)NXc * NNc);
    // Coil combine with conj sensitivities
    combine_kernel<<<(NTc * NXc * NYc) / 256, 256>>>(csmap, out);
}

// round 7
// speedup vs baseline: 1.0788x; 1.0022x over previous
#include <cuda_runtime.h>
#include <cstring>

// Problem constants
constexpr int NXc = 128, NYc = 128, NTc = 16, NCc = 8, NRADc = 2048;
constexpr int NNc = NCc * NYc;                    // 1024 fused (coil,y) columns
constexpr float SCALE2 = 1.0f / (128.0f * 128.0f); // 'ortho' scale applied twice

// Static device scratch (allocation-free per harness rules)
__device__ float2 g_Ex[NTc * NRADc * NXc];                 // 32 MB
__device__ float2 g_Ey[NTc * NRADc * NYc];                 // 32 MB
__device__ float2 g_src[NTc * NXc * NNc];                  // 16 MB
__device__ float2 g_t[(size_t)NTc * NRADc * NNc];          // 256 MB
__device__ float2 g_xim[NTc * NXc * NNc];                  // 16 MB

__device__ __forceinline__ float2 cmulf2(float2 a, float2 b) {
    return make_float2(a.x * b.x - a.y * b.y, a.x * b.y + a.y * b.x);
}

// ---- packed f32x2 helpers -------------------------------------------------
__device__ __forceinline__ unsigned long long pack2(float lo, float hi) {
    unsigned long long r;
    asm("mov.b64 %0, {%1, %2};" : "=l"(r) : "f"(lo), "f"(hi));
    return r;
}
__device__ __forceinline__ void ffma2(unsigned long long& acc,
                                      unsigned long long a, unsigned long long b) {
    asm("fma.rn.f32x2 %0, %1, %2, %0;" : "+l"(acc) : "l"(a), "l"(b));
}
__device__ __forceinline__ unsigned long long f2u(float2 v) {
    unsigned long long r; memcpy(&r, &v, 8); return r;
}
__device__ __forceinline__ float2 u2f(unsigned long long v) {
    float2 r; memcpy(&r, &v, 8); return r;
}

// ---------------------------------------------------------------------------
// K1: phase tables Ex[t][k][x] = exp(-i*k_x*(x-64)), Ey likewise.
// One warp per (t,k). One sincosf per table; powers via repeated squaring.
// ---------------------------------------------------------------------------
__global__ void phase_kernel(const float* __restrict__ ktraj) {
    int gtid = blockIdx.x * blockDim.x + threadIdx.x;
    int wid = gtid >> 5, lane = gtid & 31;
    if (wid >= NRADc * NTc) return;
    int t = wid % NTc, k = wid / NTc;

    #pragma unroll
    for (int comp = 0; comp < 2; ++comp) {
        float kv = ktraj[((size_t)comp * NRADc + k) * NTc + t];
        float s, c;
        sincosf(kv, &s, &c);
        float2 v = make_float2(c, s);        // exp(+i*kv)
        float2 pw[7];
        pw[0] = v;
        #pragma unroll
        for (int j = 1; j < 7; ++j) pw[j] = cmulf2(pw[j - 1], pw[j - 1]); // v^(2^j)
        // lane handles x = lane, lane+32, lane+64, lane+96; xs = x - 64.
        // base = exp(-i*kv*(lane-64)) = v^(64-lane), m in [33,64]
        int m = 64 - lane;
        float2 base = make_float2(1.f, 0.f);
        #pragma unroll
        for (int b = 0; b < 7; ++b)
            if ((m >> b) & 1) base = cmulf2(base, pw[b]);
        float2 step = make_float2(pw[5].x, -pw[5].y);   // exp(-i*32*kv)
        float2* out = (comp == 0 ? g_Ex : g_Ey) + ((size_t)t * NRADc + k) * 128;
        float2 cur = base;
        #pragma unroll
        for (int j = 0; j < 4; ++j) {
            out[lane + 32 * j] = cur;
            cur = cmulf2(cur, step);
        }
    }
}

// ---------------------------------------------------------------------------
// K2: src[t][x][c*NY+y] = smap[c,x,y] * img[x,y,t]
// ---------------------------------------------------------------------------
__global__ void src_kernel(const float* __restrict__ xin, const float* __restrict__ csmap) {
    int i = blockIdx.x * blockDim.x + threadIdx.x;
    if (i >= NTc * NXc * NNc) return;
    int n = i % NNc;
    int xx = (i / NNc) % NXc;
    int t = i / (NNc * NXc);
    int c = n / NYc, y = n % NYc;
    float ir = xin[(((size_t)0 * NXc + xx) * NYc + y) * NTc + t];
    float ii = xin[(((size_t)1 * NXc + xx) * NYc + y) * NTc + t];
    float sr = csmap[(((size_t)c * 2 + 0) * NXc + xx) * NYc + y];
    float si = csmap[(((size_t)c * 2 + 1) * NXc + xx) * NYc + y];
    g_src[i] = cmulf2(make_float2(sr, si), make_float2(ir, ii));
}

// ---------------------------------------------------------------------------
// Batched complex GEMM using packed f32x2 FMAs (2 real MACs / instruction).
// C[m,n] = sum_k op(A)[m,k] * B[k,n], per frame (blockIdx.z).
//   A_KMAJOR: A stored [K][M]; else [M][K]. CONJ_A: conjugate A.
// Tile: BM=64, BN=64, BK=16, 128 threads, 4x8 complex per thread.
// Each output's (Re,Im) lives in one 64-bit packed accumulator:
//   acc += (aR,aR)*(bR,bI) + (aI,aI)*(-bI,bR)
// Thread's 8 columns are stride-8 so all Bs reads are 8-address broadcasts.
// ---------------------------------------------------------------------------
template <bool A_KMAJOR, bool CONJ_A>
__global__ void __launch_bounds__(128)
cgemm_f32x2(const float2* __restrict__ A, const float2* __restrict__ B,
            float2* __restrict__ C, int M, int N, int K,
            size_t sA, size_t sB, size_t sC) {
    constexpr int BM = 64, BN = 64, BK = 16;
    __shared__ float2 As[BK][BM + 1];   // +1 kills 16-way store conflict (KMAJOR=false path)
    __shared__ float2 Bs[BK][BN];
    int f = blockIdx.z;
    A += (size_t)f * sA;
    B += (size_t)f * sB;
    C += (size_t)f * sC;
    int m0 = blockIdx.y * BM, n0 = blockIdx.x * BN;
    int tid = threadIdx.x;
    int tx = tid & 7, ty = tid >> 3;    // tx: 8 col-groups, ty: 16 row-groups

    unsigned long long acc[4][8];
    #pragma unroll
    for (int i = 0; i < 4; ++i)
        #pragma unroll
        for (int j = 0; j < 8; ++j) acc[i][j] = 0ull;

    float2 ra[8], rb[8];

    auto loadA = [&](int k0) {
        #pragma unroll
        for (int p = 0; p < 8; ++p) {
            int idx = p * 128 + tid;
            if (A_KMAJOR) {
                int kr = idx >> 6, col = idx & 63;
                ra[p] = A[(size_t)(k0 + kr) * M + m0 + col];
            } else {
                int kr = idx & 15, row = idx >> 4;
                ra[p] = A[(size_t)(m0 + row) * K + k0 + kr];
            }
        }
    };
    auto loadB = [&](int k0) {
        #pragma unroll
        for (int p = 0; p < 8; ++p) {
            int idx = p * 128 + tid;
            int kr = idx >> 6, col = idx & 63;
            rb[p] = B[(size_t)(k0 + kr) * N + n0 + col];
        }
    };
    auto stageA = [&]() {
        #pragma unroll
        for (int p = 0; p < 8; ++p) {
            int idx = p * 128 + tid;
            float2 v = ra[p];
            if (CONJ_A) v.y = -v.y;
            if (A_KMAJOR) As[idx >> 6][idx & 63] = v;
            else          As[idx & 15][idx >> 4] = v;
        }
    };
    auto stageB = [&]() {
        #pragma unroll
        for (int p = 0; p < 8; ++p) {
            int idx = p * 128 + tid;
            Bs[idx >> 6][idx & 63] = rb[p];
        }
    };

    loadA(0);
    loadB(0);

    for (int k0 = 0; k0 < K; k0 += BK) {
        stageA();
        stageB();
        __syncthreads();
        if (k0 + BK < K) { loadA(k0 + BK); loadB(k0 + BK); }

        #pragma unroll
        for (int kk = 0; kk < BK; ++kk) {
            unsigned long long b1[8], b2[8];
            #pragma unroll
            for (int j = 0; j < 8; ++j) {
                float2 b = Bs[kk][tx + 8 * j];
                b1[j] = f2u(b);
                b2[j] = pack2(-b.y, b.x);
            }
            #pragma unroll
            for (int i = 0; i < 4; ++i) {
                float2 a = As[kk][ty * 4 + i];
                unsigned long long aR = pack2(a.x, a.x);
                unsigned long long aI = pack2(a.y, a.y);
                #pragma unroll
                for (int j = 0; j < 8; ++j) {
                    ffma2(acc[i][j], aR, b1[j]);
                    ffma2(acc[i][j], aI, b2[j]);
                }
            }
        }
        __syncthreads();
    }
    #pragma unroll
    for (int i = 0; i < 4; ++i)
        #pragma unroll
        for (int j = 0; j < 8; ++j)
            C[(size_t)(m0 + ty * 4 + i) * N + n0 + tx + 8 * j] = u2f(acc[i][j]);
}

// ---------------------------------------------------------------------------
// K3 (in place on g_t): per (t,k):
//   g[c] = (sum_y Ey[k,y]*t[k,c,y]) * dcomp[k,t] * scale^2
//   t2[k,c,y] = conj(Ey[k,y]) * g[c]
// One warp per (t,k); lane covers 4 y-points.
// ---------------------------------------------------------------------------
__global__ void middle_kernel(const float* __restrict__ dcomp) {
    int gtid = blockIdx.x * blockDim.x + threadIdx.x;
    int wid = gtid >> 5, lane = gtid & 31;
    if (wid >= NRADc * NTc) return;
    int t = wid % NTc, k = wid / NTc;
    const float2* ey = g_Ey + ((size_t)t * NRADc + k) * NYc;
    float2* tp = g_t + ((size_t)t * NRADc + k) * NNc;
    float2 e[4];
    #pragma unroll
    for (int j = 0; j < 4; ++j) e[j] = ey[lane + 32 * j];
    float ds = dcomp[(size_t)k * NTc + t] * SCALE2;

    for (int c = 0; c < NCc; ++c) {
        float2 v[4];
        #pragma unroll
        for (int j = 0; j < 4; ++j) v[j] = tp[c * NYc + lane + 32 * j];
        float sr = 0.f, si = 0.f;
        #pragma unroll
        for (int j = 0; j < 4; ++j) {
            sr += e[j].x * v[j].x - e[j].y * v[j].y;
            si += e[j].x * v[j].y + e[j].y * v[j].x;
        }
        #pragma unroll
        for (int off = 16; off; off >>= 1) {
            sr += __shfl_xor_sync(0xffffffffu, sr, off);
            si += __shfl_xor_sync(0xffffffffu, si, off);
        }
        float gr = sr * ds, gi = si * ds;
        #pragma unroll
        for (int j = 0; j < 4; ++j)
            tp[c * NYc + lane + 32 * j] =
                make_float2(e[j].x * gr + e[j].y * gi, e[j].x * gi - e[j].y * gr);
    }
}

// ---------------------------------------------------------------------------
// K5: out[comp][x][y][t] = sum_c conj(smap[c,x,y]) * xim[t][x][c*NY+y]
// ---------------------------------------------------------------------------
__global__ void combine_kernel(const float* __restrict__ csmap, float* __restrict__ out) {
    int i = blockIdx.x * blockDim.x + threadIdx.x;
    if (i >= NTc * NXc * NYc) return;
    int y = i % NYc;
    int xx = (i / NYc) % NXc;
    int t = i / (NYc * NXc);
    const float2* xim = g_xim + ((size_t)t * NXc + xx) * NNc;
    float accR = 0.f, accI = 0.f;
    #pragma unroll
    for (int c = 0; c < NCc; ++c) {
        float sr = csmap[(((size_t)c * 2 + 0) * NXc + xx) * NYc + y];
        float si = csmap[(((size_t)c * 2 + 1) * NXc + xx) * NYc + y];
        float2 v = xim[c * NYc + y];
        accR += sr * v.x + si * v.y;
        accI += sr * v.y - si * v.x;
    }
    size_t o = ((size_t)xx * NYc + y) * NTc + t;
    out[o] = accR;
    out[(size_t)NXc * NYc * NTc + o] = accI;
}

// ---------------------------------------------------------------------------
extern "C" void kernel_launch(void* const* d_in, const int* in_sizes, int n_in,
                              void* d_out, int out_size) {
    // Disambiguate inputs by element count (all four are distinct)
    const float *x = nullptr, *ktraj = nullptr, *csmap = nullptr, *dcomp = nullptr;
    for (int i = 0; i < n_in; ++i) {
        switch (in_sizes[i]) {
            case 2 * NXc * NYc * NTc:      x = (const float*)d_in[i]; break;     // 524288
            case 2 * NRADc * NTc:          ktraj = (const float*)d_in[i]; break; // 65536
            case NCc * 2 * NXc * NYc:      csmap = (const float*)d_in[i]; break; // 262144
            case NRADc * NTc:              dcomp = (const float*)d_in[i]; break; // 32768
            default: break;
        }
    }
    float* out = (float*)d_out;

    float2 *pEx = nullptr, *pSrc = nullptr, *pT = nullptr, *pXim = nullptr;
    cudaGetSymbolAddress((void**)&pEx, g_Ex);
    cudaGetSymbolAddress((void**)&pSrc, g_src);
    cudaGetSymbolAddress((void**)&pT, g_t);
    cudaGetSymbolAddress((void**)&pXim, g_xim);

    // K1: phase tables (32768 warps)
    phase_kernel<<<(NRADc * NTc * 32) / 256, 256>>>(ktraj);
    // K2: coil-weighted source images
    src_kernel<<<(NTc * NXc * NNc) / 256, 256>>>(x, csmap);
    // Forward NDFT over x: t = Ex @ src   (M=2048, N=1024, K=128, per frame)
    cgemm_f32x2<false, false><<<dim3(NNc / 64, NRADc / 64, NTc), 128>>>(
        pEx, pSrc, pT, NRADc, NNc, NXc,
        (size_t)NRADc * NXc, (size_t)NXc * NNc, (size_t)NRADc * NNc);
    // Middle: Ey-projection, dcomp * scale^2, conj(Ey) expansion (in place)
    middle_kernel<<<(NRADc * NTc * 32) / 256, 256>>>(dcomp);
    // Adjoint NDFT over x: xim = conj(Ex)^T @ t2   (M=128, N=1024, K=2048)
    cgemm_f32x2<true, true><<<dim3(NNc / 64, NXc / 64, NTc), 128>>>(
        pEx, pT, pXim, NXc, NNc, NRADc,
        (size_t)NRADc * NXc, (size_t)NRADc * NNc, (size_t)NXc * NNc);
    // Coil combine with conj sensitivities
    combine_kernel<<<(NTc * NXc * NYc) / 256, 256>>>(csmap, out);
}

// round 8
// speedup vs baseline: 4.5553x; 4.2227x over previous
#include <cuda_runtime.h>
#include <cstring>

constexpr int NXc = 128, NYc = 128, NTc = 16, NCc = 8, NRADc = 2048;
constexpr float SCALE2 = 1.0f / (128.0f * 128.0f);
constexpr int KS = 8;                 // split-K chunks for T-GEMM
constexpr int KCH = NRADc / KS;       // 256

// Static device scratch
__device__ float2 g_W[128];                                   // e^{-2pi i j/256}
__device__ float2 g_Bxd[(size_t)NTc * NRADc * 256];           // e^{+i kx dx}, dx=m-128
__device__ float2 g_Byd[(size_t)NTc * NRADc * 128];           // ds * e^{+i ky dy}, dy=n
__device__ float2 g_Tsplit[(size_t)NTc * KS * 256 * 128];
__device__ float2 g_T0[(size_t)NTc * 256 * 128];
__device__ float2 g_C[(size_t)NTc * 256 * 256];               // circulant-embedded T
__device__ float2 g_TF1[(size_t)NTc * 256 * 256];
__device__ float2 g_Tspec[(size_t)NTc * 256 * 256];
__device__ float2 g_src[(size_t)NTc * NCc * 128 * 128];       // [t][c][x][y]
__device__ float2 g_F1[(size_t)NTc * NCc * 256 * 128];        // [img][yf][x<128]
__device__ float2 g_F2[(size_t)NTc * NCc * 128 * 256];        // [img][x<128][yf]
__device__ float2 g_xim[(size_t)NTc * 128 * 1024];            // [t][x][c*128+y]

__device__ __forceinline__ float2 cmulf2(float2 a, float2 b) {
    return make_float2(a.x * b.x - a.y * b.y, a.x * b.y + a.y * b.x);
}

// ---- packed f32x2 helpers for the T-GEMM ----------------------------------
__device__ __forceinline__ unsigned long long pack2(float lo, float hi) {
    unsigned long long r;
    asm("mov.b64 %0, {%1, %2};" : "=l"(r) : "f"(lo), "f"(hi));
    return r;
}
__device__ __forceinline__ void ffma2(unsigned long long& acc,
                                      unsigned long long a, unsigned long long b) {
    asm("fma.rn.f32x2 %0, %1, %2, %0;" : "+l"(acc) : "l"(a), "l"(b));
}
__device__ __forceinline__ unsigned long long f2u(float2 v) {
    unsigned long long r; memcpy(&r, &v, 8); return r;
}
__device__ __forceinline__ float2 u2f(unsigned long long v) {
    float2 r; memcpy(&r, &v, 8); return r;
}

// ---------------------------------------------------------------------------
// Twiddle table
// ---------------------------------------------------------------------------
__global__ void twiddle_kernel() {
    int j = threadIdx.x;
    if (j < 128) {
        float th = -6.283185307179586f * (float)j / 256.0f;
        float s, c;
        sincosf(th, &s, &c);
        g_W[j] = make_float2(c, s);
    }
}

// ---------------------------------------------------------------------------
// Tables: Bxd[t][k][m] = e^{i kx (m-128)} (m 0..255), Byd[t][k][n] = ds e^{i ky n}
// One warp per (t,k).
// ---------------------------------------------------------------------------
__global__ void table_kernel(const float* __restrict__ ktraj,
                             const float* __restrict__ dcomp) {
    int gtid = blockIdx.x * blockDim.x + threadIdx.x;
    int wid = gtid >> 5, lane = gtid & 31;
    if (wid >= NRADc * NTc) return;
    int t = wid % NTc, k = wid / NTc;

    // x-component
    {
        float kv = ktraj[((size_t)0 * NRADc + k) * NTc + t];
        float s, c;
        sincosf(kv, &s, &c);
        float2 w = make_float2(c, s);           // e^{+i kv}
        float2 pw[8];
        pw[0] = w;
        #pragma unroll
        for (int j = 1; j < 8; ++j) pw[j] = cmulf2(pw[j - 1], pw[j - 1]);
        int e = 128 - lane;                      // exponent magnitude, base = w^{-(128-lane)}
        float2 base = make_float2(1.f, 0.f);
        #pragma unroll
        for (int b = 0; b < 8; ++b)
            if ((e >> b) & 1) base = cmulf2(base, pw[b]);
        base.y = -base.y;                        // conj -> w^{lane-128}
        float2 step = pw[5];                     // w^{32}
        float2* out = g_Bxd + ((size_t)t * NRADc + k) * 256;
        float2 cur = base;
        #pragma unroll
        for (int j = 0; j < 8; ++j) {
            out[lane + 32 * j] = cur;
            cur = cmulf2(cur, step);
        }
    }
    // y-component with dcomp*scale^2 folded in
    {
        float kv = ktraj[((size_t)1 * NRADc + k) * NTc + t];
        float s, c;
        sincosf(kv, &s, &c);
        float2 w = make_float2(c, s);
        float2 pw[6];
        pw[0] = w;
        #pragma unroll
        for (int j = 1; j < 6; ++j) pw[j] = cmulf2(pw[j - 1], pw[j - 1]);
        float2 base = make_float2(1.f, 0.f);
        #pragma unroll
        for (int b = 0; b < 5; ++b)
            if ((lane >> b) & 1) base = cmulf2(base, pw[b]);   // w^{lane}
        float2 step = pw[5];                     // w^{32}
        float ds = dcomp[(size_t)k * NTc + t] * SCALE2;
        float2* out = g_Byd + ((size_t)t * NRADc + k) * 128;
        float2 cur = base;
        #pragma unroll
        for (int j = 0; j < 4; ++j) {
            out[lane + 32 * j] = make_float2(ds * cur.x, ds * cur.y);
            cur = cmulf2(cur, step);
        }
    }
}

// ---------------------------------------------------------------------------
// src[t][c][x][y] = smap[c,x,y] * img[x,y,t]
// ---------------------------------------------------------------------------
__global__ void src_kernel(const float* __restrict__ xin, const float* __restrict__ csmap) {
    int i = blockIdx.x * blockDim.x + threadIdx.x;
    if (i >= NTc * NCc * 128 * 128) return;
    int y = i & 127, xx = (i >> 7) & 127, c = (i >> 14) & 7, t = i >> 17;
    float ir = xin[(((size_t)0 * 128 + xx) * 128 + y) * NTc + t];
    float ii = xin[(((size_t)1 * 128 + xx) * 128 + y) * NTc + t];
    float sr = csmap[(((size_t)c * 2 + 0) * 128 + xx) * 128 + y];
    float si = csmap[(((size_t)c * 2 + 1) * 128 + xx) * 128 + y];
    g_src[i] = cmulf2(make_float2(sr, si), make_float2(ir, ii));
}

// ---------------------------------------------------------------------------
// T-GEMM (split-K): Tsplit[z][m][n] = sum_{k in chunk} Bxd[k][m] * Byd[k][n]
// M=256, N=128, BM=BN=64, BK=16, 128 threads, f32x2 packed complex MACs.
// ---------------------------------------------------------------------------
__global__ void __launch_bounds__(128)
tgemm_kernel() {
    constexpr int BK = 16;
    __shared__ float2 As[BK][65];
    __shared__ float2 Bs[BK][64];
    int z = blockIdx.z;
    int f = z >> 3, ks = z & 7;
    const float2* A = g_Bxd + ((size_t)f * NRADc + ks * KCH) * 256;
    const float2* B = g_Byd + ((size_t)f * NRADc + ks * KCH) * 128;
    float2* C = g_Tsplit + (size_t)z * 256 * 128;
    int m0 = blockIdx.y * 64, n0 = blockIdx.x * 64;
    int tid = threadIdx.x;
    int tx = tid & 7, ty = tid >> 3;

    unsigned long long acc[4][8];
    #pragma unroll
    for (int i = 0; i < 4; ++i)
        #pragma unroll
        for (int j = 0; j < 8; ++j) acc[i][j] = 0ull;

    float2 ra[8], rb[8];
    auto loadA = [&](int k0) {
        #pragma unroll
        for (int p = 0; p < 8; ++p) {
            int idx = p * 128 + tid;
            ra[p] = A[(size_t)(k0 + (idx >> 6)) * 256 + m0 + (idx & 63)];
        }
    };
    auto loadB = [&](int k0) {
        #pragma unroll
        for (int p = 0; p < 8; ++p) {
            int idx = p * 128 + tid;
            rb[p] = B[(size_t)(k0 + (idx >> 6)) * 128 + n0 + (idx & 63)];
        }
    };

    loadA(0); loadB(0);
    for (int k0 = 0; k0 < KCH; k0 += BK) {
        #pragma unroll
        for (int p = 0; p < 8; ++p) {
            int idx = p * 128 + tid;
            As[idx >> 6][idx & 63] = ra[p];
            Bs[idx >> 6][idx & 63] = rb[p];
        }
        __syncthreads();
        if (k0 + BK < KCH) { loadA(k0 + BK); loadB(k0 + BK); }

        #pragma unroll
        for (int kk = 0; kk < BK; ++kk) {
            unsigned long long b1[8], b2[8];
            #pragma unroll
            for (int j = 0; j < 8; ++j) {
                float2 b = Bs[kk][tx + 8 * j];
                b1[j] = f2u(b);
                b2[j] = pack2(-b.y, b.x);
            }
            #pragma unroll
            for (int i = 0; i < 4; ++i) {
                float2 a = As[kk][ty * 4 + i];
                unsigned long long aR = pack2(a.x, a.x);
                unsigned long long aI = pack2(a.y, a.y);
                #pragma unroll
                for (int j = 0; j < 8; ++j) {
                    ffma2(acc[i][j], aR, b1[j]);
                    ffma2(acc[i][j], aI, b2[j]);
                }
            }
        }
        __syncthreads();
    }
    #pragma unroll
    for (int i = 0; i < 4; ++i)
        #pragma unroll
        for (int j = 0; j < 8; ++j)
            C[(size_t)(m0 + ty * 4 + i) * 128 + n0 + tx + 8 * j] = u2f(acc[i][j]);
}

__global__ void treduce_kernel() {
    int i = blockIdx.x * blockDim.x + threadIdx.x;
    if (i >= NTc * 256 * 128) return;
    int f = i >> 15, e = i & 32767;
    float2 s = make_float2(0.f, 0.f);
    #pragma unroll
    for (int ks = 0; ks < KS; ++ks) {
        float2 v = g_Tsplit[((size_t)(f * KS + ks) << 15) + e];
        s.x += v.x; s.y += v.y;
    }
    g_T0[i] = s;
}

// ---------------------------------------------------------------------------
// Circulant embedding: C[t][p][q], p<->dx wrap, q<->dy wrap, Hermitian mirror.
// ---------------------------------------------------------------------------
__global__ void texpand_kernel() {
    int i = blockIdx.x * blockDim.x + threadIdx.x;
    if (i >= NTc * 256 * 256) return;
    int t = i >> 16, rem = i & 65535, p = rem >> 8, q = rem & 255;
    float2 v = make_float2(0.f, 0.f);
    if (p != 128 && q != 128) {
        int dx = (p < 128) ? p : p - 256;
        int dy = (q < 128) ? q : q - 256;
        if (dy >= 0) {
            v = g_T0[((size_t)t * 256 + (dx + 128)) * 128 + dy];
        } else {
            v = g_T0[((size_t)t * 256 + (128 - dx)) * 128 + (-dy)];
            v.y = -v.y;
        }
    }
    g_C[i] = v;
}

// ---------------------------------------------------------------------------
// 256-pt radix-2 Stockham FFT over 8 rows in smem. 256 threads.
// Result lands in buf[0]. inv = conj twiddles (no 1/N scaling).
// ---------------------------------------------------------------------------
__device__ __forceinline__ void fft_tile(float2 (*buf)[8][256], int tid, bool inv) {
    int cur = 0;
    #pragma unroll
    for (int st = 0; st < 8; ++st) {
        int s = 1 << st;
        int m = 128 >> st;
        __syncthreads();
        #pragma unroll
        for (int it = 0; it < 4; ++it) {
            int row = (tid >> 7) + 2 * it;
            int j = tid & 127;
            int q = j & (s - 1), p = j >> st;
            float2 x0 = buf[cur][row][q + s * p];
            float2 x1 = buf[cur][row][q + s * (p + m)];
            float2 w = g_W[p << st];
            if (inv) w.y = -w.y;
            float2 d = make_float2(x0.x - x1.x, x0.y - x1.y);
            buf[cur ^ 1][row][q + s * 2 * p] = make_float2(x0.x + x1.x, x0.y + x1.y);
            buf[cur ^ 1][row][q + s * (2 * p + 1)] = cmulf2(d, w);
        }
        cur ^= 1;
    }
    __syncthreads();
}

// T chain pass A: rows p (dx), FFT over q (dy), write transposed TF1[t][qf][p]
__global__ void __launch_bounds__(256) tpassA_kernel() {
    __shared__ float2 buf[2][8][256];
    int tid = threadIdx.x;
    int p0 = blockIdx.x * 8, t = blockIdx.y;
    const float2* src = g_C + (size_t)t * 65536;
    #pragma unroll
    for (int i = 0; i < 8; ++i) {
        int idx = i * 256 + tid;
        buf[0][idx >> 8][idx & 255] = src[(size_t)(p0 + (idx >> 8)) * 256 + (idx & 255)];
    }
    fft_tile(buf, tid, false);
    float2* dst = g_TF1 + (size_t)t * 65536;
    #pragma unroll
    for (int i = 0; i < 8; ++i) {
        int idx = i * 256 + tid;
        dst[(size_t)(idx >> 3) * 256 + p0 + (idx & 7)] = buf[0][idx & 7][idx >> 3];
    }
}

// T chain pass B: rows qf, FFT over p (dx), scale 1/65536, straight write Tspec
__global__ void __launch_bounds__(256) tpassB_kernel() {
    __shared__ float2 buf[2][8][256];
    int tid = threadIdx.x;
    int q0 = blockIdx.x * 8, t = blockIdx.y;
    const float2* src = g_TF1 + (size_t)t * 65536;
    #pragma unroll
    for (int i = 0; i < 8; ++i) {
        int idx = i * 256 + tid;
        buf[0][idx >> 8][idx & 255] = src[(size_t)(q0 + (idx >> 8)) * 256 + (idx & 255)];
    }
    fft_tile(buf, tid, false);
    float2* dst = g_Tspec + (size_t)t * 65536;
    const float sc = 1.0f / 65536.0f;
    #pragma unroll
    for (int i = 0; i < 8; ++i) {
        int idx = i * 256 + tid;
        float2 v = buf[0][idx >> 8][idx & 255];
        dst[(size_t)(q0 + (idx >> 8)) * 256 + (idx & 255)] = make_float2(v.x * sc, v.y * sc);
    }
}

// Image pass 1: rows x<128 of src (pad y 128->256), FFT over y, write F1[img][yf][x]
__global__ void __launch_bounds__(256) pass1_kernel() {
    __shared__ float2 buf[2][8][256];
    int tid = threadIdx.x;
    int x0 = blockIdx.x * 8, img = blockIdx.y;
    const float2* src = g_src + (size_t)img * 128 * 128;
    #pragma unroll
    for (int i = 0; i < 8; ++i) {
        int idx = i * 256 + tid;
        int r = idx >> 8, pos = idx & 255;
        buf[0][r][pos] = (pos < 128) ? src[(size_t)(x0 + r) * 128 + pos]
                                     : make_float2(0.f, 0.f);
    }
    fft_tile(buf, tid, false);
    float2* dst = g_F1 + (size_t)img * 256 * 128;
    #pragma unroll
    for (int i = 0; i < 8; ++i) {
        int idx = i * 256 + tid;
        dst[(size_t)(idx >> 3) * 128 + x0 + (idx & 7)] = buf[0][idx & 7][idx >> 3];
    }
}

// Image pass 2: rows yf, FFT over x (pad 128->256), *Tspec, IFFT over x,
// write F2[img][x<128][yf]
__global__ void __launch_bounds__(256) pass2_kernel() {
    __shared__ float2 buf[2][8][256];
    int tid = threadIdx.x;
    int yf0 = blockIdx.x * 8, img = blockIdx.y;
    int t = img >> 3;
    const float2* src = g_F1 + (size_t)img * 256 * 128;
    #pragma unroll
    for (int i = 0; i < 8; ++i) {
        int idx = i * 256 + tid;
        int r = idx >> 8, pos = idx & 255;
        buf[0][r][pos] = (pos < 128) ? src[(size_t)(yf0 + r) * 128 + pos]
                                     : make_float2(0.f, 0.f);
    }
    fft_tile(buf, tid, false);
    const float2* tsp = g_Tspec + (size_t)t * 65536;
    #pragma unroll
    for (int i = 0; i < 8; ++i) {
        int idx = i * 256 + tid;
        int r = idx >> 8, xf = idx & 255;
        buf[0][r][xf] = cmulf2(buf[0][r][xf], tsp[(size_t)(yf0 + r) * 256 + xf]);
    }
    fft_tile(buf, tid, true);
    float2* dst = g_F2 + (size_t)img * 128 * 256;
    #pragma unroll
    for (int i = 0; i < 4; ++i) {
        int idx = i * 256 + tid;        // 1024 items: x<128 only
        int x = idx >> 3, r = idx & 7;
        dst[(size_t)x * 256 + yf0 + r] = buf[0][r][x];
    }
}

// Image pass 3: rows x<128, IFFT over yf, crop y<128, write xim[t][x][c*128+y]
__global__ void __launch_bounds__(256) pass3_kernel() {
    __shared__ float2 buf[2][8][256];
    int tid = threadIdx.x;
    int x0 = blockIdx.x * 8, img = blockIdx.y;
    int t = img >> 3, c = img & 7;
    const float2* src = g_F2 + (size_t)img * 128 * 256;
    #pragma unroll
    for (int i = 0; i < 8; ++i) {
        int idx = i * 256 + tid;
        buf[0][idx >> 8][idx & 255] = src[(size_t)(x0 + (idx >> 8)) * 256 + (idx & 255)];
    }
    fft_tile(buf, tid, true);
    #pragma unroll
    for (int i = 0; i < 4; ++i) {
        int idx = i * 256 + tid;        // 1024 items
        int r = idx >> 7, y = idx & 127;
        g_xim[((size_t)(t * 128 + x0 + r)) * 1024 + c * 128 + y] = buf[0][r][y];
    }
}

// ---------------------------------------------------------------------------
// out[comp][x][y][t] = sum_c conj(smap) * xim
// ---------------------------------------------------------------------------
__global__ void combine_kernel(const float* __restrict__ csmap, float* __restrict__ out) {
    int i = blockIdx.x * blockDim.x + threadIdx.x;
    if (i >= NTc * 128 * 128) return;
    int y = i % 128, xx = (i / 128) % 128, t = i / (128 * 128);
    const float2* xim = g_xim + ((size_t)t * 128 + xx) * 1024;
    float accR = 0.f, accI = 0.f;
    #pragma unroll
    for (int c = 0; c < NCc; ++c) {
        float sr = csmap[(((size_t)c * 2 + 0) * 128 + xx) * 128 + y];
        float si = csmap[(((size_t)c * 2 + 1) * 128 + xx) * 128 + y];
        float2 v = xim[c * 128 + y];
        accR += sr * v.x + si * v.y;
        accI += sr * v.y - si * v.x;
    }
    size_t o = ((size_t)xx * 128 + y) * NTc + t;
    out[o] = accR;
    out[(size_t)128 * 128 * NTc + o] = accI;
}

// ---------------------------------------------------------------------------
extern "C" void kernel_launch(void* const* d_in, const int* in_sizes, int n_in,
                              void* d_out, int out_size) {
    const float *x = nullptr, *ktraj = nullptr, *csmap = nullptr, *dcomp = nullptr;
    for (int i = 0; i < n_in; ++i) {
        switch (in_sizes[i]) {
            case 2 * NXc * NYc * NTc:  x = (const float*)d_in[i]; break;
            case 2 * NRADc * NTc:      ktraj = (const float*)d_in[i]; break;
            case NCc * 2 * NXc * NYc:  csmap = (const float*)d_in[i]; break;
            case NRADc * NTc:          dcomp = (const float*)d_in[i]; break;
            default: break;
        }
    }
    float* out = (float*)d_out;

    twiddle_kernel<<<1, 128>>>();
    table_kernel<<<(NRADc * NTc * 32) / 256, 256>>>(ktraj, dcomp);
    src_kernel<<<(NTc * NCc * 128 * 128) / 256, 256>>>(x, csmap);
    tgemm_kernel<<<dim3(2, 4, NTc * KS), 128>>>();
    treduce_kernel<<<(NTc * 256 * 128) / 256, 256>>>();
    texpand_kernel<<<(NTc * 256 * 256) / 256, 256>>>();
    tpassA_kernel<<<dim3(32, NTc), 256>>>();
    tpassB_kernel<<<dim3(32, NTc), 256>>>();
    pass1_kernel<<<dim3(16, NTc * NCc), 256>>>();
    pass2_kernel<<<dim3(32, NTc * NCc), 256>>>();
    pass3_kernel<<<dim3(16, NTc * NCc), 256>>>();
    combine_kernel<<<(NTc * 128 * 128) / 256, 256>>>(csmap, out);
}

// round 11
// speedup vs baseline: 6.2132x; 1.3639x over previous
#include <cuda_runtime.h>
#include <cstring>

constexpr int NXc = 128, NYc = 128, NTc = 16, NCc = 8, NRADc = 2048;
constexpr float SCALE2 = 1.0f / (128.0f * 128.0f);
constexpr int KS = 8;                 // split-K chunks
constexpr int KCH = NRADc / KS;       // 256

// Static device scratch
__device__ float2 g_W[128];                                   // e^{-2pi i j/256}
__device__ float2 g_Ax[(size_t)NTc * NRADc * 128];            // (cos,sin)(kx*a), a=0..127
__device__ float2 g_By[(size_t)NTc * NRADc * 128];            // ds*(cos,sin)(ky*b)
__device__ float4 g_Ts4[(size_t)NTc * KS * 128 * 128];        // (Ccc,Ccs,Csc,Css) partials
__device__ float2 g_C[(size_t)NTc * 256 * 256];               // circulant-embedded T
__device__ float2 g_TF1[(size_t)NTc * 256 * 256];
__device__ float2 g_Tspec[(size_t)NTc * 256 * 256];
__device__ float2 g_src[(size_t)NTc * NCc * 128 * 128];       // [t][c][x][y]
__device__ float2 g_F1[(size_t)NTc * NCc * 256 * 128];        // [img][yf][x<128]
__device__ float2 g_F2[(size_t)NTc * NCc * 128 * 256];        // [img][x<128][yf]
__device__ float2 g_xim[(size_t)NTc * 128 * 1024];            // [t][x][c*128+y]

__device__ __forceinline__ float2 cmulf2(float2 a, float2 b) {
    return make_float2(a.x * b.x - a.y * b.y, a.x * b.y + a.y * b.x);
}

// ---- packed f32x2 helpers -------------------------------------------------
__device__ __forceinline__ unsigned long long pack2(float lo, float hi) {
    unsigned long long r;
    asm("mov.b64 %0, {%1, %2};" : "=l"(r) : "f"(lo), "f"(hi));
    return r;
}
__device__ __forceinline__ void ffma2(unsigned long long& acc,
                                      unsigned long long a, unsigned long long b) {
    asm("fma.rn.f32x2 %0, %1, %2, %0;" : "+l"(acc) : "l"(a), "l"(b));
}
__device__ __forceinline__ float2 u2f(unsigned long long v) {
    float2 r; memcpy(&r, &v, 8); return r;
}
__device__ __forceinline__ unsigned smem_u32(const void* p) {
    unsigned a;
    asm("{ .reg .u64 t; cvta.to.shared.u64 t, %1; cvt.u32.u64 %0, t; }" : "=r"(a) : "l"(p));
    return a;
}
__device__ __forceinline__ void cp16(unsigned dst, const void* src) {
    asm volatile("cp.async.cg.shared.global [%0], [%1], 16;" :: "r"(dst), "l"(src) : "memory");
}
#define CP_COMMIT() asm volatile("cp.async.commit_group;" ::: "memory")
#define CP_WAIT0()  asm volatile("cp.async.wait_group 0;" ::: "memory")
#define CP_WAIT1()  asm volatile("cp.async.wait_group 1;" ::: "memory")

// ---------------------------------------------------------------------------
// Twiddle table
// ---------------------------------------------------------------------------
__global__ void twiddle_kernel() {
    int j = threadIdx.x;
    if (j < 128) {
        float th = -6.283185307179586f * (float)j / 256.0f;
        float s, c;
        sincosf(th, &s, &c);
        g_W[j] = make_float2(c, s);
    }
}

// ---------------------------------------------------------------------------
// Operand tables: Ax[t][k][a] = (cos,sin)(kx*a); By[t][k][b] = ds*(cos,sin)(ky*b)
// ---------------------------------------------------------------------------
__global__ void gen_kernel(const float* __restrict__ ktraj, const float* __restrict__ dcomp) {
    int i = blockIdx.x * blockDim.x + threadIdx.x;
    int total = NTc * NRADc * 128;
    if (i >= 2 * total) return;
    int which = i >= total;
    int r = which ? i - total : i;
    int a = r & 127, k = (r >> 7) & 2047, t = r >> 18;
    float kv = ktraj[((size_t)which * NRADc + k) * NTc + t];
    float th = kv * (float)a;
    float s, c;
    sincosf(th, &s, &c);
    if (!which) {
        g_Ax[r] = make_float2(c, s);
    } else {
        float ds = dcomp[(size_t)k * NTc + t] * SCALE2;
        g_By[r] = make_float2(ds * c, ds * s);
    }
}

// ---------------------------------------------------------------------------
// src[t][c][x][y] = smap[c,x,y] * img[x,y,t]
// ---------------------------------------------------------------------------
__global__ void src_kernel(const float* __restrict__ xin, const float* __restrict__ csmap) {
    int i = blockIdx.x * blockDim.x + threadIdx.x;
    if (i >= NTc * NCc * 128 * 128) return;
    int y = i & 127, xx = (i >> 7) & 127, c = (i >> 14) & 7, t = i >> 17;
    float ir = xin[(((size_t)0 * 128 + xx) * 128 + y) * NTc + t];
    float ii = xin[(((size_t)1 * 128 + xx) * 128 + y) * NTc + t];
    float sr = csmap[(((size_t)c * 2 + 0) * 128 + xx) * 128 + y];
    float si = csmap[(((size_t)c * 2 + 1) * 128 + xx) * 128 + y];
    g_src[i] = cmulf2(make_float2(sr, si), make_float2(ir, ii));
}

// ---------------------------------------------------------------------------
// Quad-real T-GEMM (split-K, parity-folded):
//   acc1[m][n] = (Ccc,Ccs) += (ax.c,ax.c) * (by.c,by.s)
//   acc2[m][n] = (Csc,Css) += (ax.s,ax.s) * (by.c,by.s)
// M=N=128 per frame, K=256 per chunk. BM=BN=64, BK=16, 128 threads, 4x8/thread.
// cp.async double-buffered staging.
// ---------------------------------------------------------------------------
__global__ void __launch_bounds__(128) tqgemm_kernel() {
    constexpr int BK = 16;
    __shared__ float2 As[2][BK][64];
    __shared__ float2 Bs[2][BK][64];
    int z = blockIdx.z;
    int f = z >> 3, ks = z & 7;
    const float2* A = g_Ax + ((size_t)f * NRADc + ks * KCH) * 128;
    const float2* B = g_By + ((size_t)f * NRADc + ks * KCH) * 128;
    int m0 = blockIdx.y * 64, n0 = blockIdx.x * 64;
    int tid = threadIdx.x;
    int tx = tid & 7, ty = tid >> 3;

    unsigned long long acc1[4][8], acc2[4][8];
    #pragma unroll
    for (int i = 0; i < 4; ++i)
        #pragma unroll
        for (int j = 0; j < 8; ++j) { acc1[i][j] = 0ull; acc2[i][j] = 0ull; }

    unsigned sA = smem_u32(&As[0][0][0]);
    unsigned sB = smem_u32(&Bs[0][0][0]);

    auto stage = [&](int buf, int k0) {
        // 1024 float2 per array; 128 threads x 4 cp16 (2 float2 each)
        #pragma unroll
        for (int p = 0; p < 4; ++p) {
            int u = p * 128 + tid;
            int kr = u >> 5, cp = (u & 31) * 2;
            unsigned off = (unsigned)(buf * BK * 64 + kr * 64 + cp) * 8u;
            cp16(sA + off, A + (size_t)(k0 + kr) * 128 + m0 + cp);
            cp16(sB + off, B + (size_t)(k0 + kr) * 128 + n0 + cp);
        }
        CP_COMMIT();
    };

    constexpr int NCHUNK = KCH / BK;  // 16
    stage(0, 0);
    for (int c = 0; c < NCHUNK; ++c) {
        int buf = c & 1;
        if (c + 1 < NCHUNK) { stage(buf ^ 1, (c + 1) * BK); CP_WAIT1(); }
        else CP_WAIT0();
        __syncthreads();

        #pragma unroll
        for (int kk = 0; kk < BK; ++kk) {
            const unsigned long long* bp =
                reinterpret_cast<const unsigned long long*>(&Bs[buf][kk][0]);
            unsigned long long b[8];
            #pragma unroll
            for (int j = 0; j < 8; ++j) b[j] = bp[tx + 8 * j];
            #pragma unroll
            for (int i = 0; i < 4; ++i) {
                float2 a = As[buf][kk][ty * 4 + i];
                unsigned long long aC = pack2(a.x, a.x);
                unsigned long long aS = pack2(a.y, a.y);
                #pragma unroll
                for (int j = 0; j < 8; ++j) {
                    ffma2(acc1[i][j], aC, b[j]);
                    ffma2(acc2[i][j], aS, b[j]);
                }
            }
        }
        __syncthreads();
    }

    float4* C4 = g_Ts4 + (size_t)z * 128 * 128;
    #pragma unroll
    for (int i = 0; i < 4; ++i)
        #pragma unroll
        for (int j = 0; j < 8; ++j) {
            float2 v1 = u2f(acc1[i][j]);   // (Ccc, Ccs)
            float2 v2 = u2f(acc2[i][j]);   // (Csc, Css)
            C4[(size_t)(m0 + ty * 4 + i) * 128 + n0 + tx + 8 * j] =
                make_float4(v1.x, v1.y, v2.x, v2.y);
        }
}

// ---------------------------------------------------------------------------
// Fused split-K reduce + circulant embedding with parity reconstruction:
//   ReT = Ccc - sx*sy*Css ; ImT = sx*Csc + sy*Ccs
// ---------------------------------------------------------------------------
__global__ void texpand_kernel() {
    int i = blockIdx.x * blockDim.x + threadIdx.x;
    if (i >= NTc * 256 * 256) return;
    int t = i >> 16, rem = i & 65535, p = rem >> 8, q = rem & 255;
    float2 v = make_float2(0.f, 0.f);
    if (p != 128 && q != 128) {
        int dx = (p < 128) ? p : p - 256;
        int dy = (q < 128) ? q : q - 256;
        int a = dx < 0 ? -dx : dx;
        int b = dy < 0 ? -dy : dy;
        float sx = dx < 0 ? -1.f : 1.f;
        float sy = dy < 0 ? -1.f : 1.f;
        float cc = 0.f, cs = 0.f, sc = 0.f, ss = 0.f;
        size_t base = ((size_t)t * KS) * 16384 + a * 128 + b;
        #pragma unroll
        for (int ks = 0; ks < KS; ++ks) {
            float4 w = g_Ts4[base + (size_t)ks * 16384];
            cc += w.x; cs += w.y; sc += w.z; ss += w.w;
        }
        v.x = cc - sx * sy * ss;
        v.y = sx * sc + sy * cs;
    }
    g_C[i] = v;
}

// ---------------------------------------------------------------------------
// 256-pt radix-2 Stockham FFT over 8 rows in smem. 256 threads.
// ---------------------------------------------------------------------------
__device__ __forceinline__ void fft_tile(float2 (*buf)[8][256], int tid, bool inv) {
    int cur = 0;
    #pragma unroll
    for (int st = 0; st < 8; ++st) {
        int s = 1 << st;
        int m = 128 >> st;
        __syncthreads();
        #pragma unroll
        for (int it = 0; it < 4; ++it) {
            int row = (tid >> 7) + 2 * it;
            int j = tid & 127;
            int q = j & (s - 1), p = j >> st;
            float2 x0 = buf[cur][row][q + s * p];
            float2 x1 = buf[cur][row][q + s * (p + m)];
            float2 w = g_W[p << st];
            if (inv) w.y = -w.y;
            float2 d = make_float2(x0.x - x1.x, x0.y - x1.y);
            buf[cur ^ 1][row][q + s * 2 * p] = make_float2(x0.x + x1.x, x0.y + x1.y);
            buf[cur ^ 1][row][q + s * (2 * p + 1)] = cmulf2(d, w);
        }
        cur ^= 1;
    }
    __syncthreads();
}

__global__ void __launch_bounds__(256) tpassA_kernel() {
    __shared__ float2 buf[2][8][256];
    int tid = threadIdx.x;
    int p0 = blockIdx.x * 8, t = blockIdx.y;
    const float2* src = g_C + (size_t)t * 65536;
    #pragma unroll
    for (int i = 0; i < 8; ++i) {
        int idx = i * 256 + tid;
        buf[0][idx >> 8][idx & 255] = src[(size_t)(p0 + (idx >> 8)) * 256 + (idx & 255)];
    }
    fft_tile(buf, tid, false);
    float2* dst = g_TF1 + (size_t)t * 65536;
    #pragma unroll
    for (int i = 0; i < 8; ++i) {
        int idx = i * 256 + tid;
        dst[(size_t)(idx >> 3) * 256 + p0 + (idx & 7)] = buf[0][idx & 7][idx >> 3];
    }
}

__global__ void __launch_bounds__(256) tpassB_kernel() {
    __shared__ float2 buf[2][8][256];
    int tid = threadIdx.x;
    int q0 = blockIdx.x * 8, t = blockIdx.y;
    const float2* src = g_TF1 + (size_t)t * 65536;
    #pragma unroll
    for (int i = 0; i < 8; ++i) {
        int idx = i * 256 + tid;
        buf[0][idx >> 8][idx & 255] = src[(size_t)(q0 + (idx >> 8)) * 256 + (idx & 255)];
    }
    fft_tile(buf, tid, false);
    float2* dst = g_Tspec + (size_t)t * 65536;
    const float sc = 1.0f / 65536.0f;
    #pragma unroll
    for (int i = 0; i < 8; ++i) {
        int idx = i * 256 + tid;
        float2 v = buf[0][idx >> 8][idx & 255];
        dst[(size_t)(q0 + (idx >> 8)) * 256 + (idx & 255)] = make_float2(v.x * sc, v.y * sc);
    }
}

__global__ void __launch_bounds__(256) pass1_kernel() {
    __shared__ float2 buf[2][8][256];
    int tid = threadIdx.x;
    int x0 = blockIdx.x * 8, img = blockIdx.y;
    const float2* src = g_src + (size_t)img * 128 * 128;
    #pragma unroll
    for (int i = 0; i < 8; ++i) {
        int idx = i * 256 + tid;
        int r = idx >> 8, pos = idx & 255;
        buf[0][r][pos] = (pos < 128) ? src[(size_t)(x0 + r) * 128 + pos]
                                     : make_float2(0.f, 0.f);
    }
    fft_tile(buf, tid, false);
    float2* dst = g_F1 + (size_t)img * 256 * 128;
    #pragma unroll
    for (int i = 0; i < 8; ++i) {
        int idx = i * 256 + tid;
        dst[(size_t)(idx >> 3) * 128 + x0 + (idx & 7)] = buf[0][idx & 7][idx >> 3];
    }
}

__global__ void __launch_bounds__(256) pass2_kernel() {
    __shared__ float2 buf[2][8][256];
    int tid = threadIdx.x;
    int yf0 = blockIdx.x * 8, img = blockIdx.y;
    int t = img >> 3;
    const float2* src = g_F1 + (size_t)img * 256 * 128;
    #pragma unroll
    for (int i = 0; i < 8; ++i) {
        int idx = i * 256 + tid;
        int r = idx >> 8, pos = idx & 255;
        buf[0][r][pos] = (pos < 128) ? src[(size_t)(yf0 + r) * 128 + pos]
                                     : make_float2(0.f, 0.f);
    }
    fft_tile(buf, tid, false);
    const float2* tsp = g_Tspec + (size_t)t * 65536;
    #pragma unroll
    for (int i = 0; i < 8; ++i) {
        int idx = i * 256 + tid;
        int r = idx >> 8, xf = idx & 255;
        buf[0][r][xf] = cmulf2(buf[0][r][xf], tsp[(size_t)(yf0 + r) * 256 + xf]);
    }
    fft_tile(buf, tid, true);
    float2* dst = g_F2 + (size_t)img * 128 * 256;
    #pragma unroll
    for (int i = 0; i < 4; ++i) {
        int idx = i * 256 + tid;
        int x = idx >> 3, r = idx & 7;
        dst[(size_t)x * 256 + yf0 + r] = buf[0][r][x];
    }
}

__global__ void __launch_bounds__(256) pass3_kernel() {
    __shared__ float2 buf[2][8][256];
    int tid = threadIdx.x;
    int x0 = blockIdx.x * 8, img = blockIdx.y;
    int t = img >> 3, c = img & 7;
    const float2* src = g_F2 + (size_t)img * 128 * 256;
    #pragma unroll
    for (int i = 0; i < 8; ++i) {
        int idx = i * 256 + tid;
        buf[0][idx >> 8][idx & 255] = src[(size_t)(x0 + (idx >> 8)) * 256 + (idx & 255)];
    }
    fft_tile(buf, tid, true);
    #pragma unroll
    for (int i = 0; i < 4; ++i) {
        int idx = i * 256 + tid;
        int r = idx >> 7, y = idx & 127;
        g_xim[((size_t)(t * 128 + x0 + r)) * 1024 + c * 128 + y] = buf[0][r][y];
    }
}

// ---------------------------------------------------------------------------
// out[comp][x][y][t] = sum_c conj(smap) * xim
// ---------------------------------------------------------------------------
__global__ void combine_kernel(const float* __restrict__ csmap, float* __restrict__ out) {
    int i = blockIdx.x * blockDim.x + threadIdx.x;
    if (i >= NTc * 128 * 128) return;
    int y = i % 128, xx = (i / 128) % 128, t = i / (128 * 128);
    const float2* xim = g_xim + ((size_t)t * 128 + xx) * 1024;
    float accR = 0.f, accI = 0.f;
    #pragma unroll
    for (int c = 0; c < NCc; ++c) {
        float sr = csmap[(((size_t)c * 2 + 0) * 128 + xx) * 128 + y];
        float si = csmap[(((size_t)c * 2 + 1) * 128 + xx) * 128 + y];
        float2 v = xim[c * 128 + y];
        accR += sr * v.x + si * v.y;
        accI += sr * v.y - si * v.x;
    }
    size_t o = ((size_t)xx * 128 + y) * NTc + t;
    out[o] = accR;
    out[(size_t)128 * 128 * NTc + o] = accI;
}

// ---------------------------------------------------------------------------
extern "C" void kernel_launch(void* const* d_in, const int* in_sizes, int n_in,
                              void* d_out, int out_size) {
    const float *x = nullptr, *ktraj = nullptr, *csmap = nullptr, *dcomp = nullptr;
    for (int i = 0; i < n_in; ++i) {
        switch (in_sizes[i]) {
            case 2 * NXc * NYc * NTc:  x = (const float*)d_in[i]; break;
            case 2 * NRADc * NTc:      ktraj = (const float*)d_in[i]; break;
            case NCc * 2 * NXc * NYc:  csmap = (const float*)d_in[i]; break;
            case NRADc * NTc:          dcomp = (const float*)d_in[i]; break;
            default: break;
        }
    }
    float* out = (float*)d_out;

    twiddle_kernel<<<1, 128>>>();
    gen_kernel<<<(2 * NTc * NRADc * 128) / 256, 256>>>(ktraj, dcomp);
    src_kernel<<<(NTc * NCc * 128 * 128) / 256, 256>>>(x, csmap);
    tqgemm_kernel<<<dim3(2, 2, NTc * KS), 128>>>();
    texpand_kernel<<<(NTc * 256 * 256) / 256, 256>>>();
    tpassA_kernel<<<dim3(32, NTc), 256>>>();
    tpassB_kernel<<<dim3(32, NTc), 256>>>();
    pass1_kernel<<<dim3(16, NTc * NCc), 256>>>();
    pass2_kernel<<<dim3(32, NTc * NCc), 256>>>();
    pass3_kernel<<<dim3(16, NTc * NCc), 256>>>();
    combine_kernel<<<(NTc * 128 * 128) / 256, 256>>>(csmap, out);
}

// round 12
// speedup vs baseline: 6.3744x; 1.0259x over previous
#include <cuda_runtime.h>
#include <cstring>

constexpr int NXc = 128, NYc = 128, NTc = 16, NCc = 8, NRADc = 2048;
constexpr float SCALE2 = 1.0f / (128.0f * 128.0f);
constexpr int KS = 8;                 // split-K chunks
constexpr int KCH = NRADc / KS;       // 256

// Static device scratch
__device__ float2 g_W[128];                                   // e^{-2pi i j/256}
__device__ float2 g_Ax[(size_t)NTc * NRADc * 128];            // (cos,sin)(kx*a), a=0..127
__device__ float2 g_By[(size_t)NTc * NRADc * 128];            // ds*(cos,sin)(ky*b)
__device__ float4 g_Ts4[(size_t)NTc * KS * 128 * 128];        // (Ccc,Ccs,Csc,Css) partials
__device__ float2 g_C[(size_t)NTc * 256 * 256];               // circulant-embedded T
__device__ float2 g_TF1[(size_t)NTc * 256 * 256];
__device__ float2 g_Tspec[(size_t)NTc * 256 * 256];
__device__ float2 g_src[(size_t)NTc * NCc * 128 * 128];       // [t][c][x][y]
__device__ float2 g_F1[(size_t)NTc * NCc * 256 * 128];        // [img][yf][x<128]
__device__ float2 g_F2[(size_t)NTc * NCc * 128 * 256];        // [img][x<128][yf]
__device__ float2 g_xim[(size_t)NTc * 128 * 1024];            // [t][x][c*128+y]

__device__ __forceinline__ float2 cmulf2(float2 a, float2 b) {
    return make_float2(a.x * b.x - a.y * b.y, a.x * b.y + a.y * b.x);
}

// ---- packed f32x2 helpers -------------------------------------------------
__device__ __forceinline__ unsigned long long pack2(float lo, float hi) {
    unsigned long long r;
    asm("mov.b64 %0, {%1, %2};" : "=l"(r) : "f"(lo), "f"(hi));
    return r;
}
__device__ __forceinline__ void ffma2(unsigned long long& acc,
                                      unsigned long long a, unsigned long long b) {
    asm("fma.rn.f32x2 %0, %1, %2, %0;" : "+l"(acc) : "l"(a), "l"(b));
}
__device__ __forceinline__ float2 u2f(unsigned long long v) {
    float2 r; memcpy(&r, &v, 8); return r;
}
__device__ __forceinline__ unsigned smem_u32(const void* p) {
    unsigned a;
    asm("{ .reg .u64 t; cvta.to.shared.u64 t, %1; cvt.u32.u64 %0, t; }" : "=r"(a) : "l"(p));
    return a;
}
__device__ __forceinline__ void cp16(unsigned dst, const void* src) {
    asm volatile("cp.async.cg.shared.global [%0], [%1], 16;" :: "r"(dst), "l"(src) : "memory");
}
#define CP_COMMIT() asm volatile("cp.async.commit_group;" ::: "memory")
#define CP_WAIT0()  asm volatile("cp.async.wait_group 0;" ::: "memory")
#define CP_WAIT1()  asm volatile("cp.async.wait_group 1;" ::: "memory")

// ---------------------------------------------------------------------------
// Twiddle table
// ---------------------------------------------------------------------------
__global__ void twiddle_kernel() {
    int j = threadIdx.x;
    if (j < 128) {
        float th = -6.283185307179586f * (float)j / 256.0f;
        float s, c;
        sincosf(th, &s, &c);
        g_W[j] = make_float2(c, s);
    }
}

// ---------------------------------------------------------------------------
// Operand tables via warp recurrence (2 sincosf per (t,k) instead of 256):
//   Ax[t][k][a] = (cos,sin)(kx*a) = w^a, w = e^{i kx}
//   By[t][k][b] = ds*(cos,sin)(ky*b)
// One warp per (t,k); lane holds a = lane + 32*j via base w^lane, step w^32.
// ---------------------------------------------------------------------------
__global__ void gen_kernel(const float* __restrict__ ktraj, const float* __restrict__ dcomp) {
    int gtid = blockIdx.x * blockDim.x + threadIdx.x;
    int wid = gtid >> 5, lane = gtid & 31;
    if (wid >= NTc * NRADc) return;
    int t = wid % NTc, k = wid / NTc;

    #pragma unroll
    for (int comp = 0; comp < 2; ++comp) {
        float kv = ktraj[((size_t)comp * NRADc + k) * NTc + t];
        float s, c;
        sincosf(kv, &s, &c);
        float2 w = make_float2(c, s);
        float2 pw[6];
        pw[0] = w;
        #pragma unroll
        for (int j = 1; j < 6; ++j) pw[j] = cmulf2(pw[j - 1], pw[j - 1]); // w^(2^j)
        float2 base = make_float2(1.f, 0.f);
        #pragma unroll
        for (int b = 0; b < 5; ++b)
            if ((lane >> b) & 1) base = cmulf2(base, pw[b]);  // w^lane
        float2 step = pw[5];                                   // w^32
        if (comp == 0) {
            float2* out = g_Ax + ((size_t)t * NRADc + k) * 128;
            float2 cur = base;
            #pragma unroll
            for (int j = 0; j < 4; ++j) {
                out[lane + 32 * j] = cur;
                cur = cmulf2(cur, step);
            }
        } else {
            float ds = dcomp[(size_t)k * NTc + t] * SCALE2;
            float2* out = g_By + ((size_t)t * NRADc + k) * 128;
            float2 cur = base;
            #pragma unroll
            for (int j = 0; j < 4; ++j) {
                out[lane + 32 * j] = make_float2(ds * cur.x, ds * cur.y);
                cur = cmulf2(cur, step);
            }
        }
    }
}

// ---------------------------------------------------------------------------
// src[t][c][x][y] = smap[c,x,y] * img[x,y,t]
// ---------------------------------------------------------------------------
__global__ void src_kernel(const float* __restrict__ xin, const float* __restrict__ csmap) {
    int i = blockIdx.x * blockDim.x + threadIdx.x;
    if (i >= NTc * NCc * 128 * 128) return;
    int y = i & 127, xx = (i >> 7) & 127, c = (i >> 14) & 7, t = i >> 17;
    float ir = xin[(((size_t)0 * 128 + xx) * 128 + y) * NTc + t];
    float ii = xin[(((size_t)1 * 128 + xx) * 128 + y) * NTc + t];
    float sr = csmap[(((size_t)c * 2 + 0) * 128 + xx) * 128 + y];
    float si = csmap[(((size_t)c * 2 + 1) * 128 + xx) * 128 + y];
    g_src[i] = cmulf2(make_float2(sr, si), make_float2(ir, ii));
}

// ---------------------------------------------------------------------------
// Quad-real T-GEMM (split-K, parity-folded):
//   acc1[m][n] = (Ccc,Ccs) += (ax.c,ax.c) * (by.c,by.s)
//   acc2[m][n] = (Csc,Css) += (ax.s,ax.s) * (by.c,by.s)
// M=N=128 per frame, K=256 per chunk. BM=BN=64, BK=16, 128 threads, 4x8/thread.
// cp.async double-buffered staging.
// ---------------------------------------------------------------------------
__global__ void __launch_bounds__(128) tqgemm_kernel() {
    constexpr int BK = 16;
    __shared__ float2 As[2][BK][64];
    __shared__ float2 Bs[2][BK][64];
    int z = blockIdx.z;
    int f = z >> 3, ks = z & 7;
    const float2* A = g_Ax + ((size_t)f * NRADc + ks * KCH) * 128;
    const float2* B = g_By + ((size_t)f * NRADc + ks * KCH) * 128;
    int m0 = blockIdx.y * 64, n0 = blockIdx.x * 64;
    int tid = threadIdx.x;
    int tx = tid & 7, ty = tid >> 3;

    unsigned long long acc1[4][8], acc2[4][8];
    #pragma unroll
    for (int i = 0; i < 4; ++i)
        #pragma unroll
        for (int j = 0; j < 8; ++j) { acc1[i][j] = 0ull; acc2[i][j] = 0ull; }

    unsigned sA = smem_u32(&As[0][0][0]);
    unsigned sB = smem_u32(&Bs[0][0][0]);

    auto stage = [&](int buf, int k0) {
        #pragma unroll
        for (int p = 0; p < 4; ++p) {
            int u = p * 128 + tid;
            int kr = u >> 5, cp = (u & 31) * 2;
            unsigned off = (unsigned)(buf * BK * 64 + kr * 64 + cp) * 8u;
            cp16(sA + off, A + (size_t)(k0 + kr) * 128 + m0 + cp);
            cp16(sB + off, B + (size_t)(k0 + kr) * 128 + n0 + cp);
        }
        CP_COMMIT();
    };

    constexpr int NCHUNK = KCH / BK;  // 16
    stage(0, 0);
    for (int c = 0; c < NCHUNK; ++c) {
        int buf = c & 1;
        if (c + 1 < NCHUNK) { stage(buf ^ 1, (c + 1) * BK); CP_WAIT1(); }
        else CP_WAIT0();
        __syncthreads();

        #pragma unroll
        for (int kk = 0; kk < BK; ++kk) {
            const unsigned long long* bp =
                reinterpret_cast<const unsigned long long*>(&Bs[buf][kk][0]);
            unsigned long long b[8];
            #pragma unroll
            for (int j = 0; j < 8; ++j) b[j] = bp[tx + 8 * j];
            #pragma unroll
            for (int i = 0; i < 4; ++i) {
                float2 a = As[buf][kk][ty * 4 + i];
                unsigned long long aC = pack2(a.x, a.x);
                unsigned long long aS = pack2(a.y, a.y);
                #pragma unroll
                for (int j = 0; j < 8; ++j) {
                    ffma2(acc1[i][j], aC, b[j]);
                    ffma2(acc2[i][j], aS, b[j]);
                }
            }
        }
        __syncthreads();
    }

    float4* C4 = g_Ts4 + (size_t)z * 128 * 128;
    #pragma unroll
    for (int i = 0; i < 4; ++i)
        #pragma unroll
        for (int j = 0; j < 8; ++j) {
            float2 v1 = u2f(acc1[i][j]);   // (Ccc, Ccs)
            float2 v2 = u2f(acc2[i][j]);   // (Csc, Css)
            C4[(size_t)(m0 + ty * 4 + i) * 128 + n0 + tx + 8 * j] =
                make_float4(v1.x, v1.y, v2.x, v2.y);
        }
}

// ---------------------------------------------------------------------------
// Fused split-K reduce + circulant embedding with parity reconstruction:
//   ReT = Ccc - sx*sy*Css ; ImT = sx*Csc + sy*Ccs
// ---------------------------------------------------------------------------
__global__ void texpand_kernel() {
    int i = blockIdx.x * blockDim.x + threadIdx.x;
    if (i >= NTc * 256 * 256) return;
    int t = i >> 16, rem = i & 65535, p = rem >> 8, q = rem & 255;
    float2 v = make_float2(0.f, 0.f);
    if (p != 128 && q != 128) {
        int dx = (p < 128) ? p : p - 256;
        int dy = (q < 128) ? q : q - 256;
        int a = dx < 0 ? -dx : dx;
        int b = dy < 0 ? -dy : dy;
        float sx = dx < 0 ? -1.f : 1.f;
        float sy = dy < 0 ? -1.f : 1.f;
        float cc = 0.f, cs = 0.f, sc = 0.f, ss = 0.f;
        size_t base = ((size_t)t * KS) * 16384 + a * 128 + b;
        #pragma unroll
        for (int ks = 0; ks < KS; ++ks) {
            float4 w = g_Ts4[base + (size_t)ks * 16384];
            cc += w.x; cs += w.y; sc += w.z; ss += w.w;
        }
        v.x = cc - sx * sy * ss;
        v.y = sx * sc + sy * cs;
    }
    g_C[i] = v;
}

// ---------------------------------------------------------------------------
// 256-pt radix-2 Stockham FFT over 8 rows in smem. 256 threads.
// ---------------------------------------------------------------------------
__device__ __forceinline__ void fft_tile(float2 (*buf)[8][256], int tid, bool inv) {
    int cur = 0;
    #pragma unroll
    for (int st = 0; st < 8; ++st) {
        int s = 1 << st;
        int m = 128 >> st;
        __syncthreads();
        #pragma unroll
        for (int it = 0; it < 4; ++it) {
            int row = (tid >> 7) + 2 * it;
            int j = tid & 127;
            int q = j & (s - 1), p = j >> st;
            float2 x0 = buf[cur][row][q + s * p];
            float2 x1 = buf[cur][row][q + s * (p + m)];
            float2 w = g_W[p << st];
            if (inv) w.y = -w.y;
            float2 d = make_float2(x0.x - x1.x, x0.y - x1.y);
            buf[cur ^ 1][row][q + s * 2 * p] = make_float2(x0.x + x1.x, x0.y + x1.y);
            buf[cur ^ 1][row][q + s * (2 * p + 1)] = cmulf2(d, w);
        }
        cur ^= 1;
    }
    __syncthreads();
}

__global__ void __launch_bounds__(256) tpassA_kernel() {
    __shared__ float2 buf[2][8][256];
    int tid = threadIdx.x;
    int p0 = blockIdx.x * 8, t = blockIdx.y;
    const float2* src = g_C + (size_t)t * 65536;
    #pragma unroll
    for (int i = 0; i < 8; ++i) {
        int idx = i * 256 + tid;
        buf[0][idx >> 8][idx & 255] = src[(size_t)(p0 + (idx >> 8)) * 256 + (idx & 255)];
    }
    fft_tile(buf, tid, false);
    float2* dst = g_TF1 + (size_t)t * 65536;
    #pragma unroll
    for (int i = 0; i < 8; ++i) {
        int idx = i * 256 + tid;
        dst[(size_t)(idx >> 3) * 256 + p0 + (idx & 7)] = buf[0][idx & 7][idx >> 3];
    }
}

__global__ void __launch_bounds__(256) tpassB_kernel() {
    __shared__ float2 buf[2][8][256];
    int tid = threadIdx.x;
    int q0 = blockIdx.x * 8, t = blockIdx.y;
    const float2* src = g_TF1 + (size_t)t * 65536;
    #pragma unroll
    for (int i = 0; i < 8; ++i) {
        int idx = i * 256 + tid;
        buf[0][idx >> 8][idx & 255] = src[(size_t)(q0 + (idx >> 8)) * 256 + (idx & 255)];
    }
    fft_tile(buf, tid, false);
    float2* dst = g_Tspec + (size_t)t * 65536;
    const float sc = 1.0f / 65536.0f;
    #pragma unroll
    for (int i = 0; i < 8; ++i) {
        int idx = i * 256 + tid;
        float2 v = buf[0][idx >> 8][idx & 255];
        dst[(size_t)(q0 + (idx >> 8)) * 256 + (idx & 255)] = make_float2(v.x * sc, v.y * sc);
    }
}

__global__ void __launch_bounds__(256) pass1_kernel() {
    __shared__ float2 buf[2][8][256];
    int tid = threadIdx.x;
    int x0 = blockIdx.x * 8, img = blockIdx.y;
    const float2* src = g_src + (size_t)img * 128 * 128;
    #pragma unroll
    for (int i = 0; i < 8; ++i) {
        int idx = i * 256 + tid;
        int r = idx >> 8, pos = idx & 255;
        buf[0][r][pos] = (pos < 128) ? src[(size_t)(x0 + r) * 128 + pos]
                                     : make_float2(0.f, 0.f);
    }
    fft_tile(buf, tid, false);
    float2* dst = g_F1 + (size_t)img * 256 * 128;
    #pragma unroll
    for (int i = 0; i < 8; ++i) {
        int idx = i * 256 + tid;
        dst[(size_t)(idx >> 3) * 128 + x0 + (idx & 7)] = buf[0][idx & 7][idx >> 3];
    }
}

__global__ void __launch_bounds__(256) pass2_kernel() {
    __shared__ float2 buf[2][8][256];
    int tid = threadIdx.x;
    int yf0 = blockIdx.x * 8, img = blockIdx.y;
    int t = img >> 3;
    const float2* src = g_F1 + (size_t)img * 256 * 128;
    #pragma unroll
    for (int i = 0; i < 8; ++i) {
        int idx = i * 256 + tid;
        int r = idx >> 8, pos = idx & 255;
        buf[0][r][pos] = (pos < 128) ? src[(size_t)(yf0 + r) * 128 + pos]
                                     : make_float2(0.f, 0.f);
    }
    fft_tile(buf, tid, false);
    const float2* tsp = g_Tspec + (size_t)t * 65536;
    #pragma unroll
    for (int i = 0; i < 8; ++i) {
        int idx = i * 256 + tid;
        int r = idx >> 8, xf = idx & 255;
        buf[0][r][xf] = cmulf2(buf[0][r][xf], tsp[(size_t)(yf0 + r) * 256 + xf]);
    }
    fft_tile(buf, tid, true);
    float2* dst = g_F2 + (size_t)img * 128 * 256;
    #pragma unroll
    for (int i = 0; i < 4; ++i) {
        int idx = i * 256 + tid;
        int x = idx >> 3, r = idx & 7;
        dst[(size_t)x * 256 + yf0 + r] = buf[0][r][x];
    }
}

__global__ void __launch_bounds__(256) pass3_kernel() {
    __shared__ float2 buf[2][8][256];
    int tid = threadIdx.x;
    int x0 = blockIdx.x * 8, img = blockIdx.y;
    int t = img >> 3, c = img & 7;
    const float2* src = g_F2 + (size_t)img * 128 * 256;
    #pragma unroll
    for (int i = 0; i < 8; ++i) {
        int idx = i * 256 + tid;
        buf[0][idx >> 8][idx & 255] = src[(size_t)(x0 + (idx >> 8)) * 256 + (idx & 255)];
    }
    fft_tile(buf, tid, true);
    #pragma unroll
    for (int i = 0; i < 4; ++i) {
        int idx = i * 256 + tid;
        int r = idx >> 7, y = idx & 127;
        g_xim[((size_t)(t * 128 + x0 + r)) * 1024 + c * 128 + y] = buf[0][r][y];
    }
}

// ---------------------------------------------------------------------------
// out[comp][x][y][t] = sum_c conj(smap) * xim
// ---------------------------------------------------------------------------
__global__ void combine_kernel(const float* __restrict__ csmap, float* __restrict__ out) {
    int i = blockIdx.x * blockDim.x + threadIdx.x;
    if (i >= NTc * 128 * 128) return;
    int y = i % 128, xx = (i / 128) % 128, t = i / (128 * 128);
    const float2* xim = g_xim + ((size_t)t * 128 + xx) * 1024;
    float accR = 0.f, accI = 0.f;
    #pragma unroll
    for (int c = 0; c < NCc; ++c) {
        float sr = csmap[(((size_t)c * 2 + 0) * 128 + xx) * 128 + y];
        float si = csmap[(((size_t)c * 2 + 1) * 128 + xx) * 128 + y];
        float2 v = xim[c * 128 + y];
        accR += sr * v.x + si * v.y;
        accI += sr * v.y - si * v.x;
    }
    size_t o = ((size_t)xx * 128 + y) * NTc + t;
    out[o] = accR;
    out[(size_t)128 * 128 * NTc + o] = accI;
}

// ---------------------------------------------------------------------------
extern "C" void kernel_launch(void* const* d_in, const int* in_sizes, int n_in,
                              void* d_out, int out_size) {
    const float *x = nullptr, *ktraj = nullptr, *csmap = nullptr, *dcomp = nullptr;
    for (int i = 0; i < n_in; ++i) {
        switch (in_sizes[i]) {
            case 2 * NXc * NYc * NTc:  x = (const float*)d_in[i]; break;
            case 2 * NRADc * NTc:      ktraj = (const float*)d_in[i]; break;
            case NCc * 2 * NXc * NYc:  csmap = (const float*)d_in[i]; break;
            case NRADc * NTc:          dcomp = (const float*)d_in[i]; break;
            default: break;
        }
    }
    float* out = (float*)d_out;

    twiddle_kernel<<<1, 128>>>();
    gen_kernel<<<(NTc * NRADc * 32) / 256, 256>>>(ktraj, dcomp);
    src_kernel<<<(NTc * NCc * 128 * 128) / 256, 256>>>(x, csmap);
    tqgemm_kernel<<<dim3(2, 2, NTc * KS), 128>>>();
    texpand_kernel<<<(NTc * 256 * 256) / 256, 256>>>();
    tpassA_kernel<<<dim3(32, NTc), 256>>>();
    tpassB_kernel<<<dim3(32, NTc), 256>>>();
    pass1_kernel<<<dim3(16, NTc * NCc), 256>>>();
    pass2_kernel<<<dim3(32, NTc * NCc), 256>>>();
    pass3_kernel<<<dim3(16, NTc * NCc), 256>>>();
    combine_kernel<<<(NTc * 128 * 128) / 256, 256>>>(csmap, out);
}

// round 13
// speedup vs baseline: 7.1037x; 1.1144x over previous
#include <cuda_runtime.h>
#include <cstring>

constexpr int NXc = 128, NYc = 128, NTc = 16, NCc = 8, NRADc = 2048;
constexpr float SCALE2 = 1.0f / (128.0f * 128.0f);
constexpr int KS = 8;                 // split-K chunks
constexpr int KCH = NRADc / KS;       // 256

// Static device scratch
__device__ float2 g_W[128];                                   // e^{-2pi i j/256}
__device__ float2 g_Ax[(size_t)NTc * NRADc * 128];            // (cos,sin)(kx*a), a=0..127
__device__ float2 g_By[(size_t)NTc * NRADc * 128];            // ds*(cos,sin)(ky*b)
__device__ float4 g_Ts4[(size_t)NTc * KS * 128 * 128];        // (Ccc,Ccs,Csc,Css) partials
__device__ float2 g_C[(size_t)NTc * 256 * 256];               // circulant-embedded T
__device__ float2 g_TF1[(size_t)NTc * 256 * 256];
__device__ float2 g_Tspec[(size_t)NTc * 256 * 256];
__device__ float2 g_src[(size_t)NTc * NCc * 128 * 128];       // [t][c][x][y]
__device__ float2 g_F1[(size_t)NTc * NCc * 256 * 128];        // [img][yf][x<128]
__device__ float2 g_F2[(size_t)NTc * NCc * 128 * 256];        // [img][x<128][yf]
__device__ float2 g_xim[(size_t)NTc * 128 * 1024];            // [t][x][c*128+y]

__device__ __forceinline__ float2 cmulf2(float2 a, float2 b) {
    return make_float2(a.x * b.x - a.y * b.y, a.x * b.y + a.y * b.x);
}
__device__ __forceinline__ float2 caddf2(float2 a, float2 b) {
    return make_float2(a.x + b.x, a.y + b.y);
}
__device__ __forceinline__ float2 csubf2(float2 a, float2 b) {
    return make_float2(a.x - b.x, a.y - b.y);
}

// ---- packed f32x2 helpers -------------------------------------------------
__device__ __forceinline__ unsigned long long pack2(float lo, float hi) {
    unsigned long long r;
    asm("mov.b64 %0, {%1, %2};" : "=l"(r) : "f"(lo), "f"(hi));
    return r;
}
__device__ __forceinline__ void ffma2(unsigned long long& acc,
                                      unsigned long long a, unsigned long long b) {
    asm("fma.rn.f32x2 %0, %1, %2, %0;" : "+l"(acc) : "l"(a), "l"(b));
}
__device__ __forceinline__ float2 u2f(unsigned long long v) {
    float2 r; memcpy(&r, &v, 8); return r;
}
__device__ __forceinline__ unsigned smem_u32(const void* p) {
    unsigned a;
    asm("{ .reg .u64 t; cvta.to.shared.u64 t, %1; cvt.u32.u64 %0, t; }" : "=r"(a) : "l"(p));
    return a;
}
__device__ __forceinline__ void cp16(unsigned dst, const void* src) {
    asm volatile("cp.async.cg.shared.global [%0], [%1], 16;" :: "r"(dst), "l"(src) : "memory");
}
#define CP_COMMIT() asm volatile("cp.async.commit_group;" ::: "memory")
#define CP_WAIT0()  asm volatile("cp.async.wait_group 0;" ::: "memory")
#define CP_WAIT1()  asm volatile("cp.async.wait_group 1;" ::: "memory")

// ---------------------------------------------------------------------------
// Twiddle table
// ---------------------------------------------------------------------------
__global__ void twiddle_kernel() {
    int j = threadIdx.x;
    if (j < 128) {
        float th = -6.283185307179586f * (float)j / 256.0f;
        float s, c;
        sincosf(th, &s, &c);
        g_W[j] = make_float2(c, s);
    }
}

// ---------------------------------------------------------------------------
// Operand tables via warp recurrence (2 sincosf per (t,k)):
//   Ax[t][k][a] = (cos,sin)(kx*a);  By[t][k][b] = ds*(cos,sin)(ky*b)
// ---------------------------------------------------------------------------
__global__ void gen_kernel(const float* __restrict__ ktraj, const float* __restrict__ dcomp) {
    int gtid = blockIdx.x * blockDim.x + threadIdx.x;
    int wid = gtid >> 5, lane = gtid & 31;
    if (wid >= NTc * NRADc) return;
    int t = wid % NTc, k = wid / NTc;

    #pragma unroll
    for (int comp = 0; comp < 2; ++comp) {
        float kv = ktraj[((size_t)comp * NRADc + k) * NTc + t];
        float s, c;
        sincosf(kv, &s, &c);
        float2 w = make_float2(c, s);
        float2 pw[6];
        pw[0] = w;
        #pragma unroll
        for (int j = 1; j < 6; ++j) pw[j] = cmulf2(pw[j - 1], pw[j - 1]);
        float2 base = make_float2(1.f, 0.f);
        #pragma unroll
        for (int b = 0; b < 5; ++b)
            if ((lane >> b) & 1) base = cmulf2(base, pw[b]);  // w^lane
        float2 step = pw[5];                                   // w^32
        if (comp == 0) {
            float2* out = g_Ax + ((size_t)t * NRADc + k) * 128;
            float2 cur = base;
            #pragma unroll
            for (int j = 0; j < 4; ++j) {
                out[lane + 32 * j] = cur;
                cur = cmulf2(cur, step);
            }
        } else {
            float ds = dcomp[(size_t)k * NTc + t] * SCALE2;
            float2* out = g_By + ((size_t)t * NRADc + k) * 128;
            float2 cur = base;
            #pragma unroll
            for (int j = 0; j < 4; ++j) {
                out[lane + 32 * j] = make_float2(ds * cur.x, ds * cur.y);
                cur = cmulf2(cur, step);
            }
        }
    }
}

// ---------------------------------------------------------------------------
// src[t][c][x][y] = smap[c,x,y] * img[x,y,t]
// ---------------------------------------------------------------------------
__global__ void src_kernel(const float* __restrict__ xin, const float* __restrict__ csmap) {
    int i = blockIdx.x * blockDim.x + threadIdx.x;
    if (i >= NTc * NCc * 128 * 128) return;
    int y = i & 127, xx = (i >> 7) & 127, c = (i >> 14) & 7, t = i >> 17;
    float ir = xin[(((size_t)0 * 128 + xx) * 128 + y) * NTc + t];
    float ii = xin[(((size_t)1 * 128 + xx) * 128 + y) * NTc + t];
    float sr = csmap[(((size_t)c * 2 + 0) * 128 + xx) * 128 + y];
    float si = csmap[(((size_t)c * 2 + 1) * 128 + xx) * 128 + y];
    g_src[i] = cmulf2(make_float2(sr, si), make_float2(ir, ii));
}

// ---------------------------------------------------------------------------
// Quad-real T-GEMM (split-K, parity-folded) — unchanged from R11.
// ---------------------------------------------------------------------------
__global__ void __launch_bounds__(128) tqgemm_kernel() {
    constexpr int BK = 16;
    __shared__ float2 As[2][BK][64];
    __shared__ float2 Bs[2][BK][64];
    int z = blockIdx.z;
    int f = z >> 3, ks = z & 7;
    const float2* A = g_Ax + ((size_t)f * NRADc + ks * KCH) * 128;
    const float2* B = g_By + ((size_t)f * NRADc + ks * KCH) * 128;
    int m0 = blockIdx.y * 64, n0 = blockIdx.x * 64;
    int tid = threadIdx.x;
    int tx = tid & 7, ty = tid >> 3;

    unsigned long long acc1[4][8], acc2[4][8];
    #pragma unroll
    for (int i = 0; i < 4; ++i)
        #pragma unroll
        for (int j = 0; j < 8; ++j) { acc1[i][j] = 0ull; acc2[i][j] = 0ull; }

    unsigned sA = smem_u32(&As[0][0][0]);
    unsigned sB = smem_u32(&Bs[0][0][0]);

    auto stage = [&](int buf, int k0) {
        #pragma unroll
        for (int p = 0; p < 4; ++p) {
            int u = p * 128 + tid;
            int kr = u >> 5, cp = (u & 31) * 2;
            unsigned off = (unsigned)(buf * BK * 64 + kr * 64 + cp) * 8u;
            cp16(sA + off, A + (size_t)(k0 + kr) * 128 + m0 + cp);
            cp16(sB + off, B + (size_t)(k0 + kr) * 128 + n0 + cp);
        }
        CP_COMMIT();
    };

    constexpr int NCHUNK = KCH / BK;  // 16
    stage(0, 0);
    for (int c = 0; c < NCHUNK; ++c) {
        int buf = c & 1;
        if (c + 1 < NCHUNK) { stage(buf ^ 1, (c + 1) * BK); CP_WAIT1(); }
        else CP_WAIT0();
        __syncthreads();

        #pragma unroll
        for (int kk = 0; kk < BK; ++kk) {
            const unsigned long long* bp =
                reinterpret_cast<const unsigned long long*>(&Bs[buf][kk][0]);
            unsigned long long b[8];
            #pragma unroll
            for (int j = 0; j < 8; ++j) b[j] = bp[tx + 8 * j];
            #pragma unroll
            for (int i = 0; i < 4; ++i) {
                float2 a = As[buf][kk][ty * 4 + i];
                unsigned long long aC = pack2(a.x, a.x);
                unsigned long long aS = pack2(a.y, a.y);
                #pragma unroll
                for (int j = 0; j < 8; ++j) {
                    ffma2(acc1[i][j], aC, b[j]);
                    ffma2(acc2[i][j], aS, b[j]);
                }
            }
        }
        __syncthreads();
    }

    float4* C4 = g_Ts4 + (size_t)z * 128 * 128;
    #pragma unroll
    for (int i = 0; i < 4; ++i)
        #pragma unroll
        for (int j = 0; j < 8; ++j) {
            float2 v1 = u2f(acc1[i][j]);   // (Ccc, Ccs)
            float2 v2 = u2f(acc2[i][j]);   // (Csc, Css)
            C4[(size_t)(m0 + ty * 4 + i) * 128 + n0 + tx + 8 * j] =
                make_float4(v1.x, v1.y, v2.x, v2.y);
        }
}

// ---------------------------------------------------------------------------
// Fused split-K reduce + circulant embedding with parity reconstruction.
// ---------------------------------------------------------------------------
__global__ void texpand_kernel() {
    int i = blockIdx.x * blockDim.x + threadIdx.x;
    if (i >= NTc * 256 * 256) return;
    int t = i >> 16, rem = i & 65535, p = rem >> 8, q = rem & 255;
    float2 v = make_float2(0.f, 0.f);
    if (p != 128 && q != 128) {
        int dx = (p < 128) ? p : p - 256;
        int dy = (q < 128) ? q : q - 256;
        int a = dx < 0 ? -dx : dx;
        int b = dy < 0 ? -dy : dy;
        float sx = dx < 0 ? -1.f : 1.f;
        float sy = dy < 0 ? -1.f : 1.f;
        float cc = 0.f, cs = 0.f, sc = 0.f, ss = 0.f;
        size_t base = ((size_t)t * KS) * 16384 + a * 128 + b;
        #pragma unroll
        for (int ks = 0; ks < KS; ++ks) {
            float4 w = g_Ts4[base + (size_t)ks * 16384];
            cc += w.x; cs += w.y; sc += w.z; ss += w.w;
        }
        v.x = cc - sx * sy * ss;
        v.y = sx * sc + sy * cs;
    }
    g_C[i] = v;
}

// ---------------------------------------------------------------------------
// 256-pt radix-4 DIF Stockham FFT over 8 rows in smem. 256 threads, 4 stages.
// Verified against the radix-2 version on N=4 and N=16 (incl. twiddled terms).
// pad=true: stage-0 inputs at positions >=128 are structurally zero (skip loads).
// Result lands in buf[0] (even number of ping-pong flips).
// ---------------------------------------------------------------------------
__device__ __forceinline__ void fft_tile4(float2 (*buf)[8][256], int tid, bool inv, bool pad) {
    int cur = 0;
    #pragma unroll
    for (int st = 0; st < 4; ++st) {
        int s = 1 << (2 * st);          // 1, 4, 16, 64
        __syncthreads();
        #pragma unroll
        for (int it = 0; it < 2; ++it) {
            int row = (tid >> 6) + 4 * it;
            int j = tid & 63;
            int q = j & (s - 1), p = j >> (2 * st);
            int ib = q + s * p;
            float2 c0 = buf[cur][row][ib];
            float2 c1 = buf[cur][row][ib + 64];
            float2 c2, c3;
            if (pad && st == 0) {
                c2 = make_float2(0.f, 0.f);
                c3 = make_float2(0.f, 0.f);
            } else {
                c2 = buf[cur][row][ib + 128];
                c3 = buf[cur][row][ib + 192];
            }
            float2 d0 = caddf2(c0, c2);
            float2 d1 = csubf2(c0, c2);
            float2 d2 = caddf2(c1, c3);
            float2 tt = csubf2(c1, c3);
            float2 d3 = inv ? make_float2(-tt.y, tt.x)   // +i*t
                            : make_float2(tt.y, -tt.x);  // -i*t
            int e = p * s;                                // < 64
            float2 w1 = g_W[e];
            float2 w2 = g_W[2 * e];
            if (inv) { w1.y = -w1.y; w2.y = -w2.y; }
            float2 w3 = cmulf2(w1, w2);
            int ob = q + s * 4 * p;
            buf[cur ^ 1][row][ob]         = caddf2(d0, d2);
            buf[cur ^ 1][row][ob + s]     = cmulf2(caddf2(d1, d3), w1);
            buf[cur ^ 1][row][ob + 2 * s] = cmulf2(csubf2(d0, d2), w2);
            buf[cur ^ 1][row][ob + 3 * s] = cmulf2(csubf2(d1, d3), w3);
        }
        cur ^= 1;
    }
    __syncthreads();
}

__global__ void __launch_bounds__(256) tpassA_kernel() {
    __shared__ float2 buf[2][8][256];
    int tid = threadIdx.x;
    int p0 = blockIdx.x * 8, t = blockIdx.y;
    const float2* src = g_C + (size_t)t * 65536;
    #pragma unroll
    for (int i = 0; i < 8; ++i) {
        int idx = i * 256 + tid;
        buf[0][idx >> 8][idx & 255] = src[(size_t)(p0 + (idx >> 8)) * 256 + (idx & 255)];
    }
    fft_tile4(buf, tid, false, false);
    float2* dst = g_TF1 + (size_t)t * 65536;
    #pragma unroll
    for (int i = 0; i < 8; ++i) {
        int idx = i * 256 + tid;
        dst[(size_t)(idx >> 3) * 256 + p0 + (idx & 7)] = buf[0][idx & 7][idx >> 3];
    }
}

__global__ void __launch_bounds__(256) tpassB_kernel() {
    __shared__ float2 buf[2][8][256];
    int tid = threadIdx.x;
    int q0 = blockIdx.x * 8, t = blockIdx.y;
    const float2* src = g_TF1 + (size_t)t * 65536;
    #pragma unroll
    for (int i = 0; i < 8; ++i) {
        int idx = i * 256 + tid;
        buf[0][idx >> 8][idx & 255] = src[(size_t)(q0 + (idx >> 8)) * 256 + (idx & 255)];
    }
    fft_tile4(buf, tid, false, false);
    float2* dst = g_Tspec + (size_t)t * 65536;
    const float sc = 1.0f / 65536.0f;
    #pragma unroll
    for (int i = 0; i < 8; ++i) {
        int idx = i * 256 + tid;
        float2 v = buf[0][idx >> 8][idx & 255];
        dst[(size_t)(q0 + (idx >> 8)) * 256 + (idx & 255)] = make_float2(v.x * sc, v.y * sc);
    }
}

__global__ void __launch_bounds__(256) pass1_kernel() {
    __shared__ float2 buf[2][8][256];
    int tid = threadIdx.x;
    int x0 = blockIdx.x * 8, img = blockIdx.y;
    const float2* src = g_src + (size_t)img * 128 * 128;
    // only positions < 128 are read by the padded first stage
    #pragma unroll
    for (int i = 0; i < 4; ++i) {
        int idx = i * 256 + tid;           // 1024 items: 8 rows x 128
        int r = idx >> 7, pos = idx & 127;
        buf[0][r][pos] = src[(size_t)(x0 + r) * 128 + pos];
    }
    fft_tile4(buf, tid, false, true);
    float2* dst = g_F1 + (size_t)img * 256 * 128;
    #pragma unroll
    for (int i = 0; i < 8; ++i) {
        int idx = i * 256 + tid;
        dst[(size_t)(idx >> 3) * 128 + x0 + (idx & 7)] = buf[0][idx & 7][idx >> 3];
    }
}

__global__ void __launch_bounds__(256) pass2_kernel() {
    __shared__ float2 buf[2][8][256];
    int tid = threadIdx.x;
    int yf0 = blockIdx.x * 8, img = blockIdx.y;
    int t = img >> 3;
    const float2* src = g_F1 + (size_t)img * 256 * 128;
    #pragma unroll
    for (int i = 0; i < 4; ++i) {
        int idx = i * 256 + tid;           // 1024 items: 8 rows x 128
        int r = idx >> 7, pos = idx & 127;
        buf[0][r][pos] = src[(size_t)(yf0 + r) * 128 + pos];
    }
    fft_tile4(buf, tid, false, true);
    const float2* tsp = g_Tspec + (size_t)t * 65536;
    #pragma unroll
    for (int i = 0; i < 8; ++i) {
        int idx = i * 256 + tid;
        int r = idx >> 8, xf = idx & 255;
        buf[0][r][xf] = cmulf2(buf[0][r][xf], tsp[(size_t)(yf0 + r) * 256 + xf]);
    }
    fft_tile4(buf, tid, true, false);
    float2* dst = g_F2 + (size_t)img * 128 * 256;
    #pragma unroll
    for (int i = 0; i < 4; ++i) {
        int idx = i * 256 + tid;           // 1024 items: x<128 only
        int x = idx >> 3, r = idx & 7;
        dst[(size_t)x * 256 + yf0 + r] = buf[0][r][x];
    }
}

__global__ void __launch_bounds__(256) pass3_kernel() {
    __shared__ float2 buf[2][8][256];
    int tid = threadIdx.x;
    int x0 = blockIdx.x * 8, img = blockIdx.y;
    int t = img >> 3, c = img & 7;
    const float2* src = g_F2 + (size_t)img * 128 * 256;
    #pragma unroll
    for (int i = 0; i < 8; ++i) {
        int idx = i * 256 + tid;
        buf[0][idx >> 8][idx & 255] = src[(size_t)(x0 + (idx >> 8)) * 256 + (idx & 255)];
    }
    fft_tile4(buf, tid, true, false);
    #pragma unroll
    for (int i = 0; i < 4; ++i) {
        int idx = i * 256 + tid;
        int r = idx >> 7, y = idx & 127;
        g_xim[((size_t)(t * 128 + x0 + r)) * 1024 + c * 128 + y] = buf[0][r][y];
    }
}

// ---------------------------------------------------------------------------
// out[comp][x][y][t] = sum_c conj(smap) * xim
// ---------------------------------------------------------------------------
__global__ void combine_kernel(const float* __restrict__ csmap, float* __restrict__ out) {
    int i = blockIdx.x * blockDim.x + threadIdx.x;
    if (i >= NTc * 128 * 128) return;
    int y = i % 128, xx = (i / 128) % 128, t = i / (128 * 128);
    const float2* xim = g_xim + ((size_t)t * 128 + xx) * 1024;
    float accR = 0.f, accI = 0.f;
    #pragma unroll
    for (int c = 0; c < NCc; ++c) {
        float sr = csmap[(((size_t)c * 2 + 0) * 128 + xx) * 128 + y];
        float si = csmap[(((size_t)c * 2 + 1) * 128 + xx) * 128 + y];
        float2 v = xim[c * 128 + y];
        accR += sr * v.x + si * v.y;
        accI += sr * v.y - si * v.x;
    }
    size_t o = ((size_t)xx * 128 + y) * NTc + t;
    out[o] = accR;
    out[(size_t)128 * 128 * NTc + o] = accI;
}

// ---------------------------------------------------------------------------
extern "C" void kernel_launch(void* const* d_in, const int* in_sizes, int n_in,
                              void* d_out, int out_size) {
    const float *x = nullptr, *ktraj = nullptr, *csmap = nullptr, *dcomp = nullptr;
    for (int i = 0; i < n_in; ++i) {
        switch (in_sizes[i]) {
            case 2 * NXc * NYc * NTc:  x = (const float*)d_in[i]; break;
            case 2 * NRADc * NTc:      ktraj = (const float*)d_in[i]; break;
            case NCc * 2 * NXc * NYc:  csmap = (const float*)d_in[i]; break;
            case NRADc * NTc:          dcomp = (const float*)d_in[i]; break;
            default: break;
        }
    }
    float* out = (float*)d_out;

    twiddle_kernel<<<1, 128>>>();
    gen_kernel<<<(NTc * NRADc * 32) / 256, 256>>>(ktraj, dcomp);
    src_kernel<<<(NTc * NCc * 128 * 128) / 256, 256>>>(x, csmap);
    tqgemm_kernel<<<dim3(2, 2, NTc * KS), 128>>>();
    texpand_kernel<<<(NTc * 256 * 256) / 256, 256>>>();
    tpassA_kernel<<<dim3(32, NTc), 256>>>();
    tpassB_kernel<<<dim3(32, NTc), 256>>>();
    pass1_kernel<<<dim3(16, NTc * NCc), 256>>>();
    pass2_kernel<<<dim3(32, NTc * NCc), 256>>>();
    pass3_kernel<<<dim3(16, NTc * NCc), 256>>>();
    combine_kernel<<<(NTc * 128 * 128) / 256, 256>>>(csmap, out);
}